// round 9
// baseline (speedup 1.0000x reference)
#include <cuda_runtime.h>
#include <cstdint>

// ---------------------------------------------------------------------------
// TrivialGNN: 3-layer GCN
//   h1 = relu( Dh A Dh (x  @ W1) + b1 )
//   h2 = relu( Dh A Dh (h1 @ W2) + b2 )
//   out =                h2 @ Wl + bl
// where A includes self loops and Dh = diag(rsqrt(in-degree incl. self loop)).
//
// Decomposition per GCN layer:
//   s   = (X @ W) * dinv[row]          (GEMM epilogue also writes acc = s,
//                                       absorbing the self-loop term)
//   acc[c] += s[r]  for every edge     (warp-per-edge, red.global.add.v4.f32)
//   h[c]  = relu(dinv[c]*acc[c] + b)   (elementwise)
// ---------------------------------------------------------------------------

#define MAX_N 50000
#define MAX_E 640000

__device__ float g_dinv[MAX_N];           // degree, then rsqrt(degree)
__device__ float g_s  [MAX_N * 128];      // scaled features (gather source)
__device__ float g_acc[MAX_N * 128];      // scatter accumulator
__device__ float g_h  [MAX_N * 128];      // layer output
__device__ int   g_is64;                  // edge_index dtype flag

// --------------------------- dtype detection -------------------------------
// If edge_index is int64 (values < 2^31), every odd 32-bit word is 0.
// If it is int32, those words are random node indices; their sum is >> 0.
__global__ void detect_kernel(const int* __restrict__ ei) {
    if (threadIdx.x == 0 && blockIdx.x == 0) {
        long long ssum = 0;
        for (int i = 0; i < 1024; i++) ssum += (long long)ei[2 * i + 1];
        g_is64 = (ssum == 0) ? 1 : 0;
    }
}

// ----------------------------- degree pass ---------------------------------
__global__ void fill_deg(int n) {
    int i = blockIdx.x * blockDim.x + threadIdx.x;
    if (i < n) g_dinv[i] = 1.0f;          // self loop
}

__global__ void count_deg(const void* __restrict__ ei, int E) {
    int e = blockIdx.x * blockDim.x + threadIdx.x;
    if (e >= E) return;
    int c;
    if (g_is64) c = (int)((const long long*)ei)[E + e];
    else        c =       ((const int*)      ei)[E + e];
    atomicAdd(&g_dinv[c], 1.0f);
}

__global__ void rsqrt_deg(int n) {
    int i = blockIdx.x * blockDim.x + threadIdx.x;
    if (i < n) g_dinv[i] = rsqrtf(g_dinv[i]);
}

// ------------------------------- GEMM ---------------------------------------
// C[M,N] = A[M,128] @ B[128,N]
// LAYER=true : writes g_s = g_acc = C * dinv[row]        (N must be 128)
// LAYER=false: writes OUT = C + bias                      (final projection)
// Tiling: 64x64 block tile, BK=16, 256 threads, 4x4 register tile per thread.
template<int N, bool LAYER>
__global__ __launch_bounds__(256) void gemm_kernel(
    const float* __restrict__ A, const float* __restrict__ B,
    const float* __restrict__ bias, float* __restrict__ OUT, int M)
{
    __shared__ float As[64][20];   // pad 20: 80B rows -> 16B aligned, no bank clash
    __shared__ float Bs[16][64];

    const int tid = threadIdx.x;
    const int tx  = tid & 15;      // column group (4 cols each)
    const int ty  = tid >> 4;      // row group (4 rows each)
    const int blockRow = blockIdx.x * 64;
    const int blockCol = blockIdx.y * 64;

    const int arow = tid >> 2;           // 0..63
    const int akq  = (tid & 3) << 2;     // 0,4,8,12
    const int bkk  = tid >> 4;           // 0..15
    const int bcq  = (tid & 15) << 2;    // 0..60

    float acc[4][4];
#pragma unroll
    for (int i = 0; i < 4; i++)
#pragma unroll
        for (int j = 0; j < 4; j++) acc[i][j] = 0.0f;

    const int grow = blockRow + arow;
    const float* aptr = A + (size_t)grow * 128 + akq;

    for (int k0 = 0; k0 < 128; k0 += 16) {
        float4 av = make_float4(0.f, 0.f, 0.f, 0.f);
        if (grow < M) av = *(const float4*)(aptr + k0);
        *(float4*)&As[arow][akq] = av;
        *(float4*)&Bs[bkk][bcq] =
            *(const float4*)(B + (size_t)(k0 + bkk) * N + blockCol + bcq);
        __syncthreads();

#pragma unroll
        for (int kk = 0; kk < 16; kk++) {
            float4 b = *(float4*)&Bs[kk][tx << 2];
            float a0 = As[(ty << 2) + 0][kk];
            float a1 = As[(ty << 2) + 1][kk];
            float a2 = As[(ty << 2) + 2][kk];
            float a3 = As[(ty << 2) + 3][kk];
            acc[0][0] += a0 * b.x; acc[0][1] += a0 * b.y;
            acc[0][2] += a0 * b.z; acc[0][3] += a0 * b.w;
            acc[1][0] += a1 * b.x; acc[1][1] += a1 * b.y;
            acc[1][2] += a1 * b.z; acc[1][3] += a1 * b.w;
            acc[2][0] += a2 * b.x; acc[2][1] += a2 * b.y;
            acc[2][2] += a2 * b.z; acc[2][3] += a2 * b.w;
            acc[3][0] += a3 * b.x; acc[3][1] += a3 * b.y;
            acc[3][2] += a3 * b.z; acc[3][3] += a3 * b.w;
        }
        __syncthreads();
    }

#pragma unroll
    for (int i = 0; i < 4; i++) {
        const int row = blockRow + (ty << 2) + i;
        if (row >= M) continue;
        const int col = blockCol + (tx << 2);
        float4 v = make_float4(acc[i][0], acc[i][1], acc[i][2], acc[i][3]);
        if (LAYER) {
            const float d = g_dinv[row];
            v.x *= d; v.y *= d; v.z *= d; v.w *= d;
            *(float4*)(g_s   + (size_t)row * N + col) = v;   // gather source
            *(float4*)(g_acc + (size_t)row * N + col) = v;   // self-loop init
        } else {
            const float4 bb = __ldg((const float4*)(bias + col));
            v.x += bb.x; v.y += bb.y; v.z += bb.z; v.w += bb.w;
            *(float4*)(OUT + (size_t)row * N + col) = v;
        }
    }
}

// ------------------------------ edge scatter --------------------------------
// One warp per edge: 32 lanes x float4 = 512B row. s and acc are L2-resident
// (25.6 MB each), red.global.add.v4 has no return path -> L2-throughput bound.
__global__ __launch_bounds__(256) void scatter_kernel(const void* __restrict__ ei, int E) {
    const int gt   = blockIdx.x * 256 + threadIdx.x;
    const int e    = gt >> 5;
    const int lane = gt & 31;
    if (e >= E) return;

    int r, c;
    if (g_is64) {
        const long long* p = (const long long*)ei;
        r = (int)__ldg(p + e);
        c = (int)__ldg(p + E + e);
    } else {
        const int* p = (const int*)ei;
        r = __ldg(p + e);
        c = __ldg(p + E + e);
    }

    const float4 v = __ldg((const float4*)(g_s + (size_t)r * 128) + lane);
    float* dst = g_acc + (size_t)c * 128 + (lane << 2);
    asm volatile("red.global.add.v4.f32 [%0], {%1,%2,%3,%4};"
                 :: "l"(__cvta_generic_to_global(dst)),
                    "f"(v.x), "f"(v.y), "f"(v.z), "f"(v.w)
                 : "memory");
}

// ------------------------------- finalize -----------------------------------
// h[i,k] = relu(dinv[i] * acc[i,k] + b[k]); float4 per thread.
__global__ __launch_bounds__(256) void finalize_kernel(const float* __restrict__ bias, int M) {
    const int idx = blockIdx.x * 256 + threadIdx.x;    // float4 index
    if (idx >= M * 32) return;
    const int node = idx >> 5;
    const int k4   = idx & 31;
    const float d  = g_dinv[node];
    const float4 a = *(const float4*)(g_acc + ((size_t)idx << 2));
    const float4 b = __ldg((const float4*)bias + k4);
    float4 r;
    r.x = fmaxf(fmaf(d, a.x, b.x), 0.f);
    r.y = fmaxf(fmaf(d, a.y, b.y), 0.f);
    r.z = fmaxf(fmaf(d, a.z, b.z), 0.f);
    r.w = fmaxf(fmaf(d, a.w, b.w), 0.f);
    *(float4*)(g_h + ((size_t)idx << 2)) = r;
}

// ------------------------------- launch -------------------------------------
extern "C" void kernel_launch(void* const* d_in, const int* in_sizes, int n_in,
                              void* d_out, int out_size) {
    const float* x  = (const float*)d_in[0];
    const void*  ei =               d_in[1];
    const float* W1 = (const float*)d_in[2];
    const float* b1 = (const float*)d_in[3];
    const float* W2 = (const float*)d_in[4];
    const float* b2 = (const float*)d_in[5];
    const float* Wl = (const float*)d_in[6];
    const float* bl = (const float*)d_in[7];
    float* out = (float*)d_out;

    const int n = in_sizes[0] / 128;      // 50000
    const int E = in_sizes[1] / 2;        // 640000 (element count halves either dtype)

    float* h_dev = nullptr;
    cudaGetSymbolAddress((void**)&h_dev, g_h);   // host-side query, capture-safe

    // degree / normalization
    detect_kernel<<<1, 32>>>((const int*)ei);
    fill_deg <<<(n + 255) / 256, 256>>>(n);
    count_deg<<<(E + 255) / 256, 256>>>(ei, E);
    rsqrt_deg<<<(n + 255) / 256, 256>>>(n);

    const dim3 gemmGrid ((n + 63) / 64, 2);   // N=128
    const dim3 gemmGridL((n + 63) / 64, 1);   // N=64
    const int scatterBlocks = (E + 7) / 8;    // 8 edges (warps) per block
    const int finBlocks     = (n * 32 + 255) / 256;

    // layer 1
    gemm_kernel<128, true><<<gemmGrid, 256>>>(x, W1, nullptr, nullptr, n);
    scatter_kernel<<<scatterBlocks, 256>>>(ei, E);
    finalize_kernel<<<finBlocks, 256>>>(b1, n);

    // layer 2
    gemm_kernel<128, true><<<gemmGrid, 256>>>(h_dev, W2, nullptr, nullptr, n);
    scatter_kernel<<<scatterBlocks, 256>>>(ei, E);
    finalize_kernel<<<finBlocks, 256>>>(b2, n);

    // final projection
    gemm_kernel<64, false><<<gemmGridL, 256>>>(h_dev, Wl, bl, out, n);
}

// round 10
// speedup vs baseline: 1.1207x; 1.1207x over previous
#include <cuda_runtime.h>
#include <cstdint>

// ---------------------------------------------------------------------------
// TrivialGNN: 3-layer GCN.
// Per GCN layer:
//   s = (X @ W) * dinv[row]                     (128x128-tile SGEMM, fused scale)
//   h[c] = relu( dinv[c] * (s[c] + sum_{r->c} s[r]) + b )
// The neighbor sum uses a CSR built by counting sort on the destination
// column (histogram -> prefix scan -> atomic placement), then one warp per
// node gathers neighbor rows (L2-resident) and writes the output once.
// ---------------------------------------------------------------------------

#define MAX_N 50000
#define MAX_E 640000

__device__ float g_dinv[MAX_N];        // rsqrt(in-degree incl. self loop)
__device__ float g_s  [MAX_N * 128];   // scaled features (gather source)
__device__ float g_h  [MAX_N * 128];   // layer output
__device__ int   g_cnt[MAX_N];         // per-destination edge count
__device__ int   g_off[MAX_N + 1];     // CSR offsets (exclusive scan of cnt)
__device__ int   g_cur[MAX_N];         // placement cursors
__device__ int   g_csr[MAX_E];         // source node per CSR slot
__device__ int   g_is64;               // edge_index dtype flag

// --------------------------- dtype detection -------------------------------
// int64 indices < 2^31 -> every odd 32-bit word is zero. int32 -> random.
__global__ void detect_kernel(const int* __restrict__ ei) {
    if (threadIdx.x == 0 && blockIdx.x == 0) {
        long long ssum = 0;
        for (int i = 0; i < 1024; i++) ssum += (long long)ei[2 * i + 1];
        g_is64 = (ssum == 0) ? 1 : 0;
    }
}

__device__ __forceinline__ void load_edge(const void* ei, int E, int e,
                                          int& r, int& c) {
    if (g_is64) {
        const long long* p = (const long long*)ei;
        r = (int)__ldg(p + e);
        c = (int)__ldg(p + E + e);
    } else {
        const int* p = (const int*)ei;
        r = __ldg(p + e);
        c = __ldg(p + E + e);
    }
}

// ------------------------------ CSR build ----------------------------------
__global__ void hist_kernel(const void* __restrict__ ei, int E) {
    int e = blockIdx.x * blockDim.x + threadIdx.x;
    if (e >= E) return;
    int r, c; load_edge(ei, E, e, r, c);
    atomicAdd(&g_cnt[c], 1);
}

// Single-block exclusive scan over g_cnt -> g_off, g_cur. Also g_off[n].
__global__ __launch_bounds__(1024) void scan_kernel(int n) {
    __shared__ int sh[32];
    __shared__ int carry_s;
    const int tid  = threadIdx.x;
    const int lane = tid & 31;
    const int warp = tid >> 5;
    if (tid == 0) carry_s = 0;
    __syncthreads();

    for (int base = 0; base < n; base += 1024) {
        const int i = base + tid;
        const int v = (i < n) ? g_cnt[i] : 0;
        int x = v;
#pragma unroll
        for (int o = 1; o < 32; o <<= 1) {
            int y = __shfl_up_sync(0xffffffffu, x, o);
            if (lane >= o) x += y;
        }
        if (lane == 31) sh[warp] = x;
        __syncthreads();
        if (tid < 32) {
            int w = sh[tid];
#pragma unroll
            for (int o = 1; o < 32; o <<= 1) {
                int y = __shfl_up_sync(0xffffffffu, w, o);
                if (tid >= o) w += y;
            }
            sh[tid] = w;
        }
        __syncthreads();
        const int pre  = (warp > 0) ? sh[warp - 1] : 0;
        const int incl = x + pre + carry_s;
        if (i < n) { g_off[i] = incl - v; g_cur[i] = incl - v; }
        __syncthreads();
        if (tid == 1023) carry_s = incl;
        __syncthreads();
    }
    if (tid == 0) g_off[n] = carry_s;
}

__global__ void dinv_kernel(int n) {
    int i = blockIdx.x * blockDim.x + threadIdx.x;
    if (i < n) g_dinv[i] = rsqrtf((float)g_cnt[i] + 1.0f);  // +1 = self loop
}

__global__ void fillcsr_kernel(const void* __restrict__ ei, int E) {
    int e = blockIdx.x * blockDim.x + threadIdx.x;
    if (e >= E) return;
    int r, c; load_edge(ei, E, e, r, c);
    int pos = atomicAdd(&g_cur[c], 1);
    g_csr[pos] = r;
}

// ------------------------------- GEMM ---------------------------------------
// C[M,TN] = A[M,128] @ B[128,TN], 128xTN block tile, BK=8, 256 threads,
// 8x(TN/16) microtile, register-staged global prefetch.
// LAYER=true : g_s[row] = C[row] * dinv[row]
// LAYER=false: OUT = C + bias
template<int TN, bool LAYER>
__global__ __launch_bounds__(256) void gemm_kernel(
    const float* __restrict__ A, const float* __restrict__ B,
    const float* __restrict__ bias, float* __restrict__ OUT, int M)
{
    constexpr int TCN = TN / 16;           // cols per thread (8 or 4)
    __shared__ float As[8][132];           // transposed, pad 132 -> no conflicts
    __shared__ float Bs[8][TN];

    const int tid = threadIdx.x;
    const int tx  = tid & 15;              // column group
    const int ty  = tid >> 4;              // row group
    const int blockRow = blockIdx.x * 128;

    // A staging: thread -> (row, 4 k's)
    const int arow = tid >> 1;
    const int akq  = (tid & 1) << 2;
    const int grow = blockRow + arow;
    const bool aok = (grow < M);
    const float* aptr = A + (size_t)grow * 128 + akq;

    // B staging
    int bk, bc; bool bok;
    if (TN == 128) { bk = tid >> 5; bc = (tid & 31) << 2; bok = true; }
    else           { bk = tid >> 4; bc = (tid & 15) << 2; bok = (tid < 128); }

    float acc[8][TCN];
#pragma unroll
    for (int i = 0; i < 8; i++)
#pragma unroll
        for (int j = 0; j < TCN; j++) acc[i][j] = 0.0f;

    float4 aNext = make_float4(0.f, 0.f, 0.f, 0.f);
    float4 bNext = make_float4(0.f, 0.f, 0.f, 0.f);
    if (aok) aNext = *(const float4*)aptr;
    if (bok) bNext = *(const float4*)(B + (size_t)bk * TN + bc);

    for (int k0 = 0; k0 < 128; k0 += 8) {
        As[akq + 0][arow] = aNext.x;
        As[akq + 1][arow] = aNext.y;
        As[akq + 2][arow] = aNext.z;
        As[akq + 3][arow] = aNext.w;
        if (bok) *(float4*)&Bs[bk][bc] = bNext;
        __syncthreads();

        if (k0 + 8 < 128) {   // prefetch next tile; latency hidden by FMAs
            if (aok) aNext = *(const float4*)(aptr + k0 + 8);
            if (bok) bNext = *(const float4*)(B + (size_t)(k0 + 8 + bk) * TN + bc);
        }

#pragma unroll
        for (int kk = 0; kk < 8; kk++) {
            float a[8];
            *(float4*)&a[0] = *(const float4*)&As[kk][ty * 8];
            *(float4*)&a[4] = *(const float4*)&As[kk][ty * 8 + 4];
            float b[TCN];
            if (TN == 128) {
                *(float4*)&b[0] = *(const float4*)&Bs[kk][tx * 8];
                *(float4*)&b[4] = *(const float4*)&Bs[kk][tx * 8 + 4];
            } else {
                *(float4*)&b[0] = *(const float4*)&Bs[kk][tx * 4];
            }
#pragma unroll
            for (int i = 0; i < 8; i++)
#pragma unroll
                for (int j = 0; j < TCN; j++)
                    acc[i][j] = fmaf(a[i], b[j], acc[i][j]);
        }
        __syncthreads();
    }

#pragma unroll
    for (int i = 0; i < 8; i++) {
        const int row = blockRow + ty * 8 + i;
        if (row >= M) continue;
        if (LAYER) {
            const float d = g_dinv[row];
            float* dst = g_s + (size_t)row * TN + tx * TCN;
#pragma unroll
            for (int j4 = 0; j4 < TCN; j4 += 4) {
                float4 v = make_float4(acc[i][j4] * d, acc[i][j4 + 1] * d,
                                       acc[i][j4 + 2] * d, acc[i][j4 + 3] * d);
                *(float4*)(dst + j4) = v;
            }
        } else {
            const int col = tx * TCN;
            float* dst = OUT + (size_t)row * TN + col;
#pragma unroll
            for (int j4 = 0; j4 < TCN; j4 += 4) {
                const float4 bb = __ldg((const float4*)(bias + col + j4));
                float4 v = make_float4(acc[i][j4] + bb.x, acc[i][j4 + 1] + bb.y,
                                       acc[i][j4 + 2] + bb.z, acc[i][j4 + 3] + bb.w);
                *(float4*)(dst + j4) = v;
            }
        }
    }
}

// --------------------------- neighbor aggregation ---------------------------
// One warp per node. Each lane owns a float4 of the 128-wide row. Gathers
// neighbor rows of g_s (L2-resident), adds the self term, applies dinv, bias,
// relu, and writes g_h once. Unroll-by-4 for memory-level parallelism.
__global__ __launch_bounds__(256) void aggregate_kernel(
    const float* __restrict__ bias, int n)
{
    const int node = (blockIdx.x * 256 + threadIdx.x) >> 5;
    const int lane = threadIdx.x & 31;
    if (node >= n) return;

    float4 acc = __ldg((const float4*)(g_s + (size_t)node * 128) + lane); // self
    int i = g_off[node];
    const int end = g_off[node + 1];

    for (; i + 4 <= end; i += 4) {
        const int r0 = __ldg(&g_csr[i]);
        const int r1 = __ldg(&g_csr[i + 1]);
        const int r2 = __ldg(&g_csr[i + 2]);
        const int r3 = __ldg(&g_csr[i + 3]);
        const float4 v0 = __ldg((const float4*)(g_s + (size_t)r0 * 128) + lane);
        const float4 v1 = __ldg((const float4*)(g_s + (size_t)r1 * 128) + lane);
        const float4 v2 = __ldg((const float4*)(g_s + (size_t)r2 * 128) + lane);
        const float4 v3 = __ldg((const float4*)(g_s + (size_t)r3 * 128) + lane);
        acc.x += (v0.x + v1.x) + (v2.x + v3.x);
        acc.y += (v0.y + v1.y) + (v2.y + v3.y);
        acc.z += (v0.z + v1.z) + (v2.z + v3.z);
        acc.w += (v0.w + v1.w) + (v2.w + v3.w);
    }
    for (; i < end; i++) {
        const int r = __ldg(&g_csr[i]);
        const float4 v = __ldg((const float4*)(g_s + (size_t)r * 128) + lane);
        acc.x += v.x; acc.y += v.y; acc.z += v.z; acc.w += v.w;
    }

    const float d = g_dinv[node];
    const float4 b = __ldg((const float4*)bias + lane);
    float4 r;
    r.x = fmaxf(fmaf(d, acc.x, b.x), 0.f);
    r.y = fmaxf(fmaf(d, acc.y, b.y), 0.f);
    r.z = fmaxf(fmaf(d, acc.z, b.z), 0.f);
    r.w = fmaxf(fmaf(d, acc.w, b.w), 0.f);
    *((float4*)(g_h + (size_t)node * 128) + lane) = r;
}

// ------------------------------- launch -------------------------------------
extern "C" void kernel_launch(void* const* d_in, const int* in_sizes, int n_in,
                              void* d_out, int out_size) {
    const float* x  = (const float*)d_in[0];
    const void*  ei =               d_in[1];
    const float* W1 = (const float*)d_in[2];
    const float* b1 = (const float*)d_in[3];
    const float* W2 = (const float*)d_in[4];
    const float* b2 = (const float*)d_in[5];
    const float* Wl = (const float*)d_in[6];
    const float* bl = (const float*)d_in[7];
    float* out = (float*)d_out;

    const int n = in_sizes[0] / 128;   // 50000
    const int E = in_sizes[1] / 2;     // 640000

    float* h_dev = nullptr;  cudaGetSymbolAddress((void**)&h_dev, g_h);
    int*   cnt_dev = nullptr; cudaGetSymbolAddress((void**)&cnt_dev, g_cnt);

    const int eB = (E + 255) / 256;
    const int nB = (n + 255) / 256;
    const int gemmBlocks = (n + 127) / 128;
    const int aggBlocks  = (n * 32 + 255) / 256;   // warp per node

    // ---- CSR + normalization build ----
    detect_kernel<<<1, 32>>>((const int*)ei);
    cudaMemsetAsync(cnt_dev, 0, (size_t)n * sizeof(int));
    hist_kernel<<<eB, 256>>>(ei, E);
    scan_kernel<<<1, 1024>>>(n);
    dinv_kernel<<<nB, 256>>>(n);
    fillcsr_kernel<<<eB, 256>>>(ei, E);

    // ---- layer 1 ----
    gemm_kernel<128, true><<<gemmBlocks, 256>>>(x, W1, nullptr, nullptr, n);
    aggregate_kernel<<<aggBlocks, 256>>>(b1, n);

    // ---- layer 2 ----
    gemm_kernel<128, true><<<gemmBlocks, 256>>>(h_dev, W2, nullptr, nullptr, n);
    aggregate_kernel<<<aggBlocks, 256>>>(b2, n);

    // ---- final projection ----
    gemm_kernel<64, false><<<gemmBlocks, 256>>>(h_dev, Wl, bl, out, n);
}

// round 11
// speedup vs baseline: 1.4138x; 1.2615x over previous
#include <cuda_runtime.h>
#include <cstdint>

// ---------------------------------------------------------------------------
// TrivialGNN: 3-layer GCN.
// Per GCN layer:
//   s = (X @ W) * dinv[row]       (tensor-core 3xTF32 GEMM, fused scale)
//   h[c] = relu( dinv[c] * (s[c] + sum_{r->c} s[r]) + b )
// Neighbor sum via CSR (counting sort by destination), one warp per node,
// gather from L2-resident g_s, single output write.
// GEMMs run on the tensor pipe: mma.sync.m16n8k8 tf32 with the 3xTF32
// error-compensation scheme (A_hi*B_hi + A_lo*B_hi + A_hi*B_lo) -> ~fp32
// accuracy at tensor-core speed. hi/lo split done once at SMEM staging.
// ---------------------------------------------------------------------------

#define MAX_N 50000
#define MAX_E 640000

__device__ float g_dinv[MAX_N];        // rsqrt(in-degree incl. self loop)
__device__ float g_s  [MAX_N * 128];   // scaled features (gather source)
__device__ float g_h  [MAX_N * 128];   // layer output
__device__ int   g_cnt[MAX_N];         // per-destination edge count
__device__ int   g_off[MAX_N + 1];     // CSR offsets
__device__ int   g_cur[MAX_N];         // placement cursors
__device__ int   g_csr[MAX_E];         // source node per CSR slot
__device__ int   g_is64;               // edge_index dtype flag

// --------------------------- dtype detection -------------------------------
__global__ void detect_kernel(const int* __restrict__ ei) {
    if (threadIdx.x == 0 && blockIdx.x == 0) {
        long long ssum = 0;
        for (int i = 0; i < 1024; i++) ssum += (long long)ei[2 * i + 1];
        g_is64 = (ssum == 0) ? 1 : 0;
    }
}

__device__ __forceinline__ void load_edge(const void* ei, int E, int e,
                                          int& r, int& c) {
    if (g_is64) {
        const long long* p = (const long long*)ei;
        r = (int)__ldg(p + e);
        c = (int)__ldg(p + E + e);
    } else {
        const int* p = (const int*)ei;
        r = __ldg(p + e);
        c = __ldg(p + E + e);
    }
}

// ------------------------------ CSR build ----------------------------------
__global__ void hist_kernel(const void* __restrict__ ei, int E) {
    int e = blockIdx.x * blockDim.x + threadIdx.x;
    if (e >= E) return;
    int r, c; load_edge(ei, E, e, r, c);
    atomicAdd(&g_cnt[c], 1);
}

__global__ __launch_bounds__(1024) void scan_kernel(int n) {
    __shared__ int sh[32];
    __shared__ int carry_s;
    const int tid  = threadIdx.x;
    const int lane = tid & 31;
    const int warp = tid >> 5;
    if (tid == 0) carry_s = 0;
    __syncthreads();

    for (int base = 0; base < n; base += 1024) {
        const int i = base + tid;
        const int v = (i < n) ? g_cnt[i] : 0;
        int x = v;
#pragma unroll
        for (int o = 1; o < 32; o <<= 1) {
            int y = __shfl_up_sync(0xffffffffu, x, o);
            if (lane >= o) x += y;
        }
        if (lane == 31) sh[warp] = x;
        __syncthreads();
        if (tid < 32) {
            int w = sh[tid];
#pragma unroll
            for (int o = 1; o < 32; o <<= 1) {
                int y = __shfl_up_sync(0xffffffffu, w, o);
                if (tid >= o) w += y;
            }
            sh[tid] = w;
        }
        __syncthreads();
        const int pre  = (warp > 0) ? sh[warp - 1] : 0;
        const int incl = x + pre + carry_s;
        if (i < n) { g_off[i] = incl - v; g_cur[i] = incl - v; }
        __syncthreads();
        if (tid == 1023) carry_s = incl;
        __syncthreads();
    }
    if (tid == 0) g_off[n] = carry_s;
}

__global__ void dinv_kernel(int n) {
    int i = blockIdx.x * blockDim.x + threadIdx.x;
    if (i < n) g_dinv[i] = rsqrtf((float)g_cnt[i] + 1.0f);
}

__global__ void fillcsr_kernel(const void* __restrict__ ei, int E) {
    int e = blockIdx.x * blockDim.x + threadIdx.x;
    if (e >= E) return;
    int r, c; load_edge(ei, E, e, r, c);
    int pos = atomicAdd(&g_cur[c], 1);
    g_csr[pos] = r;
}

// --------------------------- 3xTF32 tensor GEMM -----------------------------
__device__ __forceinline__ float tf32_rn(float x) {
    uint32_t u;
    asm("cvt.rna.tf32.f32 %0, %1;" : "=r"(u) : "f"(x));
    return __uint_as_float(u);
}
__device__ __forceinline__ void split4(float4 v, float4& h, float4& l) {
    h.x = tf32_rn(v.x); l.x = tf32_rn(v.x - h.x);
    h.y = tf32_rn(v.y); l.y = tf32_rn(v.y - h.y);
    h.z = tf32_rn(v.z); l.z = tf32_rn(v.z - h.z);
    h.w = tf32_rn(v.w); l.w = tf32_rn(v.w - h.w);
}

#define MMA_TF32(c, a, b)                                                   \
    asm volatile("mma.sync.aligned.m16n8k8.row.col.f32.tf32.tf32.f32 "     \
                 "{%0,%1,%2,%3}, {%4,%5,%6,%7}, {%8,%9}, {%0,%1,%2,%3};"   \
                 : "+f"((c)[0]), "+f"((c)[1]), "+f"((c)[2]), "+f"((c)[3])  \
                 : "r"((a)[0]), "r"((a)[1]), "r"((a)[2]), "r"((a)[3]),     \
                   "r"((b)[0]), "r"((b)[1]))

// C[M,TN] = A[M,128] @ B[128,TN].
// Block: 128 x TN tile, 256 threads (8 warps), K chunked by 64 in SMEM.
// LAYER=true : g_s[row] = C[row] * dinv[row]
// LAYER=false: OUT = C + bias
template<int TN, bool LAYER>
__global__ __launch_bounds__(256, 1) void mma_gemm(
    const float* __restrict__ A, const float* __restrict__ B,
    const float* __restrict__ bias, float* __restrict__ OUT, int M)
{
    constexpr int WM = (TN == 128) ? 2 : 4;   // warps along M
    constexpr int WN = 8 / WM;                // warps along N
    constexpr int MT = 128 / WM / 16;         // m16 tiles per warp
    constexpr int NT = TN / WN / 8;           // n8 tiles per warp
    constexpr int SA = 68;                    // A smem stride (64 + 4 pad)
    constexpr int SB = TN + 8;                // B smem stride

    extern __shared__ float smf[];
    float* As_hi = smf;                       // [128][SA]
    float* As_lo = As_hi + 128 * SA;
    float* Bs_hi = As_lo + 128 * SA;          // [64][SB]
    float* Bs_lo = Bs_hi + 64 * SB;

    const int tid    = threadIdx.x;
    const int warpId = tid >> 5;
    const int lane   = tid & 31;
    const int g      = lane >> 2;             // group id (0..7)
    const int tg     = lane & 3;              // thread in group (0..3)
    const int wm     = warpId % WM;
    const int wn     = warpId / WM;
    const int blockRow = blockIdx.x * 128;
    constexpr int RPW = 128 / WM;             // rows per warp
    constexpr int CPW = TN / WN;              // cols per warp

    float acc[MT][NT][4];
#pragma unroll
    for (int mi = 0; mi < MT; mi++)
#pragma unroll
        for (int ni = 0; ni < NT; ni++)
#pragma unroll
            for (int q = 0; q < 4; q++) acc[mi][ni][q] = 0.0f;

    for (int k0 = 0; k0 < 128; k0 += 64) {
        // ---- stage A chunk: 128 rows x 64 k ----
#pragma unroll
        for (int it = 0; it < 8; it++) {
            const int s   = tid + it * 256;       // 2048 float4 slots
            const int row = s >> 4;
            const int c4  = (s & 15) << 2;
            float4 v = make_float4(0.f, 0.f, 0.f, 0.f);
            if (blockRow + row < M)
                v = *(const float4*)(A + (size_t)(blockRow + row) * 128 + k0 + c4);
            float4 h, l; split4(v, h, l);
            *(float4*)&As_hi[row * SA + c4] = h;
            *(float4*)&As_lo[row * SA + c4] = l;
        }
        // ---- stage B chunk: 64 k x TN ----
#pragma unroll
        for (int it = 0; it < (64 * TN / 4) / 256; it++) {
            const int s   = tid + it * 256;
            const int row = s / (TN / 4);
            const int c4  = (s % (TN / 4)) << 2;
            float4 v = *(const float4*)(B + (size_t)(k0 + row) * TN + c4);
            float4 h, l; split4(v, h, l);
            *(float4*)&Bs_hi[row * SB + c4] = h;
            *(float4*)&Bs_lo[row * SB + c4] = l;
        }
        __syncthreads();

#pragma unroll
        for (int kk = 0; kk < 8; kk++) {
            const int kb = kk * 8;
            uint32_t ah[MT][4], al[MT][4];
#pragma unroll
            for (int mi = 0; mi < MT; mi++) {
                const int r0 = wm * RPW + mi * 16 + g;
                const int c0 = kb + tg;
                ah[mi][0] = __float_as_uint(As_hi[(size_t)r0 * SA + c0]);
                ah[mi][1] = __float_as_uint(As_hi[(size_t)(r0 + 8) * SA + c0]);
                ah[mi][2] = __float_as_uint(As_hi[(size_t)r0 * SA + c0 + 4]);
                ah[mi][3] = __float_as_uint(As_hi[(size_t)(r0 + 8) * SA + c0 + 4]);
                al[mi][0] = __float_as_uint(As_lo[(size_t)r0 * SA + c0]);
                al[mi][1] = __float_as_uint(As_lo[(size_t)(r0 + 8) * SA + c0]);
                al[mi][2] = __float_as_uint(As_lo[(size_t)r0 * SA + c0 + 4]);
                al[mi][3] = __float_as_uint(As_lo[(size_t)(r0 + 8) * SA + c0 + 4]);
            }
            uint32_t bh[NT][2], bl[NT][2];
#pragma unroll
            for (int ni = 0; ni < NT; ni++) {
                const int col = wn * CPW + ni * 8 + g;
                bh[ni][0] = __float_as_uint(Bs_hi[(size_t)(kb + tg) * SB + col]);
                bh[ni][1] = __float_as_uint(Bs_hi[(size_t)(kb + tg + 4) * SB + col]);
                bl[ni][0] = __float_as_uint(Bs_lo[(size_t)(kb + tg) * SB + col]);
                bl[ni][1] = __float_as_uint(Bs_lo[(size_t)(kb + tg + 4) * SB + col]);
            }
#pragma unroll
            for (int mi = 0; mi < MT; mi++)
#pragma unroll
                for (int ni = 0; ni < NT; ni++) {
                    MMA_TF32(acc[mi][ni], ah[mi], bh[ni]);
                    MMA_TF32(acc[mi][ni], al[mi], bh[ni]);
                    MMA_TF32(acc[mi][ni], ah[mi], bl[ni]);
                }
        }
        __syncthreads();
    }

    // ---- epilogue ----
#pragma unroll
    for (int mi = 0; mi < MT; mi++) {
        const int rbase = blockRow + wm * RPW + mi * 16;
        const int r0 = rbase + g;
        const int r1 = rbase + g + 8;
        if (LAYER) {
            const float d0 = (r0 < M) ? g_dinv[r0] : 0.f;
            const float d1 = (r1 < M) ? g_dinv[r1] : 0.f;
#pragma unroll
            for (int ni = 0; ni < NT; ni++) {
                const int col = wn * CPW + ni * 8 + tg * 2;
                if (r0 < M) {
                    float2 v = make_float2(acc[mi][ni][0] * d0, acc[mi][ni][1] * d0);
                    *(float2*)(g_s + (size_t)r0 * TN + col) = v;
                }
                if (r1 < M) {
                    float2 v = make_float2(acc[mi][ni][2] * d1, acc[mi][ni][3] * d1);
                    *(float2*)(g_s + (size_t)r1 * TN + col) = v;
                }
            }
        } else {
#pragma unroll
            for (int ni = 0; ni < NT; ni++) {
                const int col = wn * CPW + ni * 8 + tg * 2;
                const float2 bb = __ldg((const float2*)(bias + col));
                if (r0 < M) {
                    float2 v = make_float2(acc[mi][ni][0] + bb.x, acc[mi][ni][1] + bb.y);
                    *(float2*)(OUT + (size_t)r0 * TN + col) = v;
                }
                if (r1 < M) {
                    float2 v = make_float2(acc[mi][ni][2] + bb.x, acc[mi][ni][3] + bb.y);
                    *(float2*)(OUT + (size_t)r1 * TN + col) = v;
                }
            }
        }
    }
}

// --------------------------- neighbor aggregation ---------------------------
__global__ __launch_bounds__(256) void aggregate_kernel(
    const float* __restrict__ bias, int n)
{
    const int node = (blockIdx.x * 256 + threadIdx.x) >> 5;
    const int lane = threadIdx.x & 31;
    if (node >= n) return;

    float4 acc = __ldg((const float4*)(g_s + (size_t)node * 128) + lane); // self
    int i = g_off[node];
    const int end = g_off[node + 1];

    for (; i + 4 <= end; i += 4) {
        const int r0 = __ldg(&g_csr[i]);
        const int r1 = __ldg(&g_csr[i + 1]);
        const int r2 = __ldg(&g_csr[i + 2]);
        const int r3 = __ldg(&g_csr[i + 3]);
        const float4 v0 = __ldg((const float4*)(g_s + (size_t)r0 * 128) + lane);
        const float4 v1 = __ldg((const float4*)(g_s + (size_t)r1 * 128) + lane);
        const float4 v2 = __ldg((const float4*)(g_s + (size_t)r2 * 128) + lane);
        const float4 v3 = __ldg((const float4*)(g_s + (size_t)r3 * 128) + lane);
        acc.x += (v0.x + v1.x) + (v2.x + v3.x);
        acc.y += (v0.y + v1.y) + (v2.y + v3.y);
        acc.z += (v0.z + v1.z) + (v2.z + v3.z);
        acc.w += (v0.w + v1.w) + (v2.w + v3.w);
    }
    for (; i < end; i++) {
        const int r = __ldg(&g_csr[i]);
        const float4 v = __ldg((const float4*)(g_s + (size_t)r * 128) + lane);
        acc.x += v.x; acc.y += v.y; acc.z += v.z; acc.w += v.w;
    }

    const float d = g_dinv[node];
    const float4 b = __ldg((const float4*)bias + lane);
    float4 r;
    r.x = fmaxf(fmaf(d, acc.x, b.x), 0.f);
    r.y = fmaxf(fmaf(d, acc.y, b.y), 0.f);
    r.z = fmaxf(fmaf(d, acc.z, b.z), 0.f);
    r.w = fmaxf(fmaf(d, acc.w, b.w), 0.f);
    *((float4*)(g_h + (size_t)node * 128) + lane) = r;
}

// ------------------------------- launch -------------------------------------
extern "C" void kernel_launch(void* const* d_in, const int* in_sizes, int n_in,
                              void* d_out, int out_size) {
    const float* x  = (const float*)d_in[0];
    const void*  ei =               d_in[1];
    const float* W1 = (const float*)d_in[2];
    const float* b1 = (const float*)d_in[3];
    const float* W2 = (const float*)d_in[4];
    const float* b2 = (const float*)d_in[5];
    const float* Wl = (const float*)d_in[6];
    const float* bl = (const float*)d_in[7];
    float* out = (float*)d_out;

    const int n = in_sizes[0] / 128;   // 50000
    const int E = in_sizes[1] / 2;     // 640000

    float* h_dev = nullptr;  cudaGetSymbolAddress((void**)&h_dev, g_h);
    int*   cnt_dev = nullptr; cudaGetSymbolAddress((void**)&cnt_dev, g_cnt);

    // dynamic SMEM sizes for the GEMMs
    const int smem128 = (128 * 68 * 2 + 64 * 136 * 2) * 4;   // 139264 B
    const int smem64  = (128 * 68 * 2 + 64 * 72  * 2) * 4;   // 106496 B
    static bool attr_done = false;
    if (!attr_done) {
        cudaFuncSetAttribute(mma_gemm<128, true>,
                             cudaFuncAttributeMaxDynamicSharedMemorySize, smem128);
        cudaFuncSetAttribute(mma_gemm<64, false>,
                             cudaFuncAttributeMaxDynamicSharedMemorySize, smem64);
        attr_done = true;
    }

    const int eB = (E + 255) / 256;
    const int nB = (n + 255) / 256;
    const int gemmBlocks = (n + 127) / 128;
    const int aggBlocks  = (n * 32 + 255) / 256;

    // ---- CSR + normalization build ----
    detect_kernel<<<1, 32>>>((const int*)ei);
    cudaMemsetAsync(cnt_dev, 0, (size_t)n * sizeof(int));
    hist_kernel<<<eB, 256>>>(ei, E);
    scan_kernel<<<1, 1024>>>(n);
    dinv_kernel<<<nB, 256>>>(n);
    fillcsr_kernel<<<eB, 256>>>(ei, E);

    // ---- layer 1 ----
    mma_gemm<128, true><<<gemmBlocks, 256, smem128>>>(x, W1, nullptr, nullptr, n);
    aggregate_kernel<<<aggBlocks, 256>>>(b1, n);

    // ---- layer 2 ----
    mma_gemm<128, true><<<gemmBlocks, 256, smem128>>>(h_dev, W2, nullptr, nullptr, n);
    aggregate_kernel<<<aggBlocks, 256>>>(b2, n);

    // ---- final projection ----
    mma_gemm<64, false><<<gemmBlocks, 256, smem64>>>(h_dev, Wl, bl, out, n);
}

// round 12
// speedup vs baseline: 1.6516x; 1.1682x over previous
#include <cuda_runtime.h>
#include <cuda_bf16.h>
#include <cstdint>

// ---------------------------------------------------------------------------
// TrivialGNN: 3-layer GCN.
// Per GCN layer:
//   s = (X @ W) * dinv[row]       (tensor-core bf16x3 GEMM, fused scale)
//   h[c] = relu( dinv[c] * (s[c] + sum_{r->c} s[r]) + b )
// Neighbor sum via CSR (counting sort by destination), one warp per node,
// gather from L2-resident g_s, single output write.
// GEMMs: mma.sync.m16n8k16 bf16 with the bf16x3 error-compensation scheme
// (ah*bh + al*bh + ah*bl where a = a_hi + a_lo in bf16) -> ~1e-5 accuracy at
// full bf16 tensor rate. hi/lo split done once at SMEM staging; the whole
// K=128 tile is staged once per CTA.
// ---------------------------------------------------------------------------

#define MAX_N 50000
#define MAX_E 640000

__device__ float g_dinv[MAX_N];        // rsqrt(in-degree incl. self loop)
__device__ float g_s  [MAX_N * 128];   // scaled features (gather source)
__device__ float g_h  [MAX_N * 128];   // layer output
__device__ int   g_cnt[MAX_N];         // per-destination edge count
__device__ int   g_off[MAX_N + 1];     // CSR offsets
__device__ int   g_cur[MAX_N];         // placement cursors
__device__ int   g_csr[MAX_E];         // source node per CSR slot
__device__ int   g_is64;               // edge_index dtype flag

// ----------------------- zero counts + dtype detect -------------------------
__global__ void zero_detect_kernel(const int* __restrict__ ei, int n) {
    int i = blockIdx.x * blockDim.x + threadIdx.x;
    if (i < n) g_cnt[i] = 0;
    if (i == 0) {
        long long ssum = 0;
        for (int k = 0; k < 1024; k++) ssum += (long long)ei[2 * k + 1];
        g_is64 = (ssum == 0) ? 1 : 0;
    }
}

__device__ __forceinline__ void load_edge(const void* ei, int E, int e,
                                          int& r, int& c) {
    if (g_is64) {
        const long long* p = (const long long*)ei;
        r = (int)__ldg(p + e);
        c = (int)__ldg(p + E + e);
    } else {
        const int* p = (const int*)ei;
        r = __ldg(p + e);
        c = __ldg(p + E + e);
    }
}

// ------------------------------ CSR build ----------------------------------
__global__ void hist_kernel(const void* __restrict__ ei, int E) {
    int e = blockIdx.x * blockDim.x + threadIdx.x;
    if (e >= E) return;
    int r, c; load_edge(ei, E, e, r, c);
    atomicAdd(&g_cnt[c], 1);
}

// Single-block exclusive scan over g_cnt -> g_off/g_cur, plus dinv.
__global__ __launch_bounds__(1024) void scan_kernel(int n) {
    __shared__ int sh[32];
    __shared__ int carry_s;
    const int tid  = threadIdx.x;
    const int lane = tid & 31;
    const int warp = tid >> 5;
    if (tid == 0) carry_s = 0;
    __syncthreads();

    for (int base = 0; base < n; base += 1024) {
        const int i = base + tid;
        const int v = (i < n) ? g_cnt[i] : 0;
        int x = v;
#pragma unroll
        for (int o = 1; o < 32; o <<= 1) {
            int y = __shfl_up_sync(0xffffffffu, x, o);
            if (lane >= o) x += y;
        }
        if (lane == 31) sh[warp] = x;
        __syncthreads();
        if (tid < 32) {
            int w = sh[tid];
#pragma unroll
            for (int o = 1; o < 32; o <<= 1) {
                int y = __shfl_up_sync(0xffffffffu, w, o);
                if (tid >= o) w += y;
            }
            sh[tid] = w;
        }
        __syncthreads();
        const int pre  = (warp > 0) ? sh[warp - 1] : 0;
        const int incl = x + pre + carry_s;
        if (i < n) {
            g_off[i] = incl - v;
            g_cur[i] = incl - v;
            g_dinv[i] = rsqrtf((float)v + 1.0f);   // +1 = self loop
        }
        __syncthreads();
        if (tid == 1023) carry_s = incl;
        __syncthreads();
    }
    if (tid == 0) g_off[n] = carry_s;
}

__global__ void fillcsr_kernel(const void* __restrict__ ei, int E) {
    int e = blockIdx.x * blockDim.x + threadIdx.x;
    if (e >= E) return;
    int r, c; load_edge(ei, E, e, r, c);
    int pos = atomicAdd(&g_cur[c], 1);
    g_csr[pos] = r;
}

// --------------------------- bf16x3 tensor GEMM -----------------------------
// Split a float pair into packed bf16x2 hi and lo words (low half = first elem).
__device__ __forceinline__ void pack2(float x, float y,
                                      uint32_t& h, uint32_t& l) {
    __nv_bfloat16 hx = __float2bfloat16_rn(x);
    __nv_bfloat16 hy = __float2bfloat16_rn(y);
    float rx = x - __bfloat162float(hx);
    float ry = y - __bfloat162float(hy);
    __nv_bfloat16 lx = __float2bfloat16_rn(rx);
    __nv_bfloat16 ly = __float2bfloat16_rn(ry);
    h = (uint32_t)*(uint16_t*)&hx | ((uint32_t)*(uint16_t*)&hy << 16);
    l = (uint32_t)*(uint16_t*)&lx | ((uint32_t)*(uint16_t*)&ly << 16);
}

#define MMA_BF16(c, a, b)                                                    \
    asm volatile("mma.sync.aligned.m16n8k16.row.col.f32.bf16.bf16.f32 "      \
                 "{%0,%1,%2,%3}, {%4,%5,%6,%7}, {%8,%9}, {%0,%1,%2,%3};"     \
                 : "+f"((c)[0]), "+f"((c)[1]), "+f"((c)[2]), "+f"((c)[3])    \
                 : "r"((a)[0]), "r"((a)[1]), "r"((a)[2]), "r"((a)[3]),       \
                   "r"((b)[0]), "r"((b)[1]))

// C[M,TN] = A[M,128] @ B[128,TN]. 128 x TN block tile, 256 threads (8 warps),
// full K=128 staged once in SMEM as packed-bf16 hi/lo (A row-major, B
// col-major), word stride 68 -> conflict-free fragment loads (bank = 4g+tg).
// LAYER=true : g_s[row] = C[row] * dinv[row]
// LAYER=false: OUT = C + bias
template<int TN, bool LAYER>
__global__ __launch_bounds__(256, 1) void mma_gemm(
    const float* __restrict__ A, const float* __restrict__ B,
    const float* __restrict__ bias, float* __restrict__ OUT, int M)
{
    constexpr int WM  = (TN == 128) ? 2 : 4;   // warps along M
    constexpr int WN  = 8 / WM;                // warps along N
    constexpr int MT  = 128 / WM / 16;         // m16 tiles per warp
    constexpr int NT  = TN / WN / 8;           // n8 tiles per warp
    constexpr int RPW = 128 / WM;
    constexpr int CPW = TN / WN;
    constexpr int SW  = 68;                    // SMEM word stride (64 + 4 pad)

    extern __shared__ uint32_t smw[];
    uint32_t* As_hi = smw;                     // [128][SW] packed bf16x2
    uint32_t* As_lo = As_hi + 128 * SW;
    uint32_t* Bs_hi = As_lo + 128 * SW;        // [TN][SW] col-major (k packed)
    uint32_t* Bs_lo = Bs_hi + TN * SW;

    const int tid    = threadIdx.x;
    const int warpId = tid >> 5;
    const int lane   = tid & 31;
    const int g      = lane >> 2;
    const int tg     = lane & 3;
    const int wm     = warpId % WM;
    const int wn     = warpId / WM;
    const int blockRow = blockIdx.x * 128;

    // ---- stage A: 128 rows x 128 k, split to hi/lo ----
#pragma unroll
    for (int it = 0; it < 16; it++) {
        const int s   = tid + it * 256;        // 4096 float4 items
        const int row = s >> 5;
        const int c4  = (s & 31) << 2;
        float4 v = make_float4(0.f, 0.f, 0.f, 0.f);
        if (blockRow + row < M)
            v = *(const float4*)(A + (size_t)(blockRow + row) * 128 + c4);
        uint32_t h0, l0, h1, l1;
        pack2(v.x, v.y, h0, l0);
        pack2(v.z, v.w, h1, l1);
        const int w = row * SW + ((s & 31) << 1);
        *(uint2*)&As_hi[w] = make_uint2(h0, h1);
        *(uint2*)&As_lo[w] = make_uint2(l0, l1);
    }
    // ---- stage B transposed: Bs[col][k], 4 k per item ----
#pragma unroll
    for (int it = 0; it < TN / 8; it++) {
        const int s   = tid + it * 256;        // 32*TN items
        const int col = s & (TN - 1);
        const int kb  = (s / TN) << 2;
        const float b0 = B[(size_t)(kb + 0) * TN + col];
        const float b1 = B[(size_t)(kb + 1) * TN + col];
        const float b2 = B[(size_t)(kb + 2) * TN + col];
        const float b3 = B[(size_t)(kb + 3) * TN + col];
        uint32_t h0, l0, h1, l1;
        pack2(b0, b1, h0, l0);
        pack2(b2, b3, h1, l1);
        const int w = col * SW + (kb >> 1);
        *(uint2*)&Bs_hi[w] = make_uint2(h0, h1);
        *(uint2*)&Bs_lo[w] = make_uint2(l0, l1);
    }
    __syncthreads();

    float acc[MT][NT][4];
#pragma unroll
    for (int mi = 0; mi < MT; mi++)
#pragma unroll
        for (int ni = 0; ni < NT; ni++)
#pragma unroll
            for (int q = 0; q < 4; q++) acc[mi][ni][q] = 0.0f;

#pragma unroll
    for (int kk = 0; kk < 8; kk++) {           // k16 steps over K=128
        uint32_t ah[MT][4], al[MT][4];
#pragma unroll
        for (int mi = 0; mi < MT; mi++) {
            const int base = (wm * RPW + mi * 16 + g) * SW + kk * 8 + tg;
            ah[mi][0] = As_hi[base];
            ah[mi][1] = As_hi[base + 8 * SW];
            ah[mi][2] = As_hi[base + 4];
            ah[mi][3] = As_hi[base + 8 * SW + 4];
            al[mi][0] = As_lo[base];
            al[mi][1] = As_lo[base + 8 * SW];
            al[mi][2] = As_lo[base + 4];
            al[mi][3] = As_lo[base + 8 * SW + 4];
        }
        uint32_t bh[NT][2], bl[NT][2];
#pragma unroll
        for (int ni = 0; ni < NT; ni++) {
            const int base = (wn * CPW + ni * 8 + g) * SW + kk * 8 + tg;
            bh[ni][0] = Bs_hi[base];
            bh[ni][1] = Bs_hi[base + 4];
            bl[ni][0] = Bs_lo[base];
            bl[ni][1] = Bs_lo[base + 4];
        }
#pragma unroll
        for (int mi = 0; mi < MT; mi++)
#pragma unroll
            for (int ni = 0; ni < NT; ni++) {
                MMA_BF16(acc[mi][ni], ah[mi], bh[ni]);
                MMA_BF16(acc[mi][ni], al[mi], bh[ni]);
                MMA_BF16(acc[mi][ni], ah[mi], bl[ni]);
            }
    }

    // ---- epilogue (m16n8 C layout: c0/c1 row g, c2/c3 row g+8) ----
#pragma unroll
    for (int mi = 0; mi < MT; mi++) {
        const int rbase = blockRow + wm * RPW + mi * 16;
        const int r0 = rbase + g;
        const int r1 = rbase + g + 8;
        if (LAYER) {
            const float d0 = (r0 < M) ? g_dinv[r0] : 0.f;
            const float d1 = (r1 < M) ? g_dinv[r1] : 0.f;
#pragma unroll
            for (int ni = 0; ni < NT; ni++) {
                const int col = wn * CPW + ni * 8 + tg * 2;
                if (r0 < M) {
                    float2 v = make_float2(acc[mi][ni][0] * d0, acc[mi][ni][1] * d0);
                    *(float2*)(g_s + (size_t)r0 * TN + col) = v;
                }
                if (r1 < M) {
                    float2 v = make_float2(acc[mi][ni][2] * d1, acc[mi][ni][3] * d1);
                    *(float2*)(g_s + (size_t)r1 * TN + col) = v;
                }
            }
        } else {
#pragma unroll
            for (int ni = 0; ni < NT; ni++) {
                const int col = wn * CPW + ni * 8 + tg * 2;
                const float2 bb = __ldg((const float2*)(bias + col));
                if (r0 < M) {
                    float2 v = make_float2(acc[mi][ni][0] + bb.x, acc[mi][ni][1] + bb.y);
                    *(float2*)(OUT + (size_t)r0 * TN + col) = v;
                }
                if (r1 < M) {
                    float2 v = make_float2(acc[mi][ni][2] + bb.x, acc[mi][ni][3] + bb.y);
                    *(float2*)(OUT + (size_t)r1 * TN + col) = v;
                }
            }
        }
    }
}

// --------------------------- neighbor aggregation ---------------------------
__global__ __launch_bounds__(256) void aggregate_kernel(
    const float* __restrict__ bias, int n)
{
    const int node = (blockIdx.x * 256 + threadIdx.x) >> 5;
    const int lane = threadIdx.x & 31;
    if (node >= n) return;

    float4 acc = __ldg((const float4*)(g_s + (size_t)node * 128) + lane); // self
    int i = g_off[node];
    const int end = g_off[node + 1];

    for (; i + 4 <= end; i += 4) {
        const int r0 = __ldg(&g_csr[i]);
        const int r1 = __ldg(&g_csr[i + 1]);
        const int r2 = __ldg(&g_csr[i + 2]);
        const int r3 = __ldg(&g_csr[i + 3]);
        const float4 v0 = __ldg((const float4*)(g_s + (size_t)r0 * 128) + lane);
        const float4 v1 = __ldg((const float4*)(g_s + (size_t)r1 * 128) + lane);
        const float4 v2 = __ldg((const float4*)(g_s + (size_t)r2 * 128) + lane);
        const float4 v3 = __ldg((const float4*)(g_s + (size_t)r3 * 128) + lane);
        acc.x += (v0.x + v1.x) + (v2.x + v3.x);
        acc.y += (v0.y + v1.y) + (v2.y + v3.y);
        acc.z += (v0.z + v1.z) + (v2.z + v3.z);
        acc.w += (v0.w + v1.w) + (v2.w + v3.w);
    }
    for (; i < end; i++) {
        const int r = __ldg(&g_csr[i]);
        const float4 v = __ldg((const float4*)(g_s + (size_t)r * 128) + lane);
        acc.x += v.x; acc.y += v.y; acc.z += v.z; acc.w += v.w;
    }

    const float d = g_dinv[node];
    const float4 b = __ldg((const float4*)bias + lane);
    float4 r;
    r.x = fmaxf(fmaf(d, acc.x, b.x), 0.f);
    r.y = fmaxf(fmaf(d, acc.y, b.y), 0.f);
    r.z = fmaxf(fmaf(d, acc.z, b.z), 0.f);
    r.w = fmaxf(fmaf(d, acc.w, b.w), 0.f);
    *((float4*)(g_h + (size_t)node * 128) + lane) = r;
}

// ------------------------------- launch -------------------------------------
extern "C" void kernel_launch(void* const* d_in, const int* in_sizes, int n_in,
                              void* d_out, int out_size) {
    const float* x  = (const float*)d_in[0];
    const void*  ei =               d_in[1];
    const float* W1 = (const float*)d_in[2];
    const float* b1 = (const float*)d_in[3];
    const float* W2 = (const float*)d_in[4];
    const float* b2 = (const float*)d_in[5];
    const float* Wl = (const float*)d_in[6];
    const float* bl = (const float*)d_in[7];
    float* out = (float*)d_out;

    const int n = in_sizes[0] / 128;   // 50000
    const int E = in_sizes[1] / 2;     // 640000

    float* h_dev = nullptr;  cudaGetSymbolAddress((void**)&h_dev, g_h);

    // dynamic SMEM: A hi/lo (128*68 words each) + B hi/lo (TN*68 words each)
    const int smem128 = (128 * 68 * 2 + 128 * 68 * 2) * 4;   // 139264 B
    const int smem64  = (128 * 68 * 2 +  64 * 68 * 2) * 4;   // 104448 B
    static bool attr_done = false;
    if (!attr_done) {
        cudaFuncSetAttribute(mma_gemm<128, true>,
                             cudaFuncAttributeMaxDynamicSharedMemorySize, smem128);
        cudaFuncSetAttribute(mma_gemm<64, false>,
                             cudaFuncAttributeMaxDynamicSharedMemorySize, smem64);
        attr_done = true;
    }

    const int eB = (E + 255) / 256;
    const int nB = (n + 255) / 256;
    const int gemmBlocks = (n + 127) / 128;
    const int aggBlocks  = (n * 32 + 255) / 256;

    // ---- CSR + normalization build (4 launches) ----
    zero_detect_kernel<<<nB, 256>>>((const int*)ei, n);
    hist_kernel<<<eB, 256>>>(ei, E);
    scan_kernel<<<1, 1024>>>(n);
    fillcsr_kernel<<<eB, 256>>>(ei, E);

    // ---- layer 1 ----
    mma_gemm<128, true><<<gemmBlocks, 256, smem128>>>(x, W1, nullptr, nullptr, n);
    aggregate_kernel<<<aggBlocks, 256>>>(b1, n);

    // ---- layer 2 ----
    mma_gemm<128, true><<<gemmBlocks, 256, smem128>>>(h_dev, W2, nullptr, nullptr, n);
    aggregate_kernel<<<aggBlocks, 256>>>(b2, n);

    // ---- final projection ----
    mma_gemm<64, false><<<gemmBlocks, 256, smem64>>>(h_dev, Wl, bl, out, n);
}

// round 13
// speedup vs baseline: 1.8653x; 1.1294x over previous
#include <cuda_runtime.h>
#include <cuda_bf16.h>
#include <cstdint>

// ---------------------------------------------------------------------------
// TrivialGNN: 3-layer GCN.
// Per GCN layer:
//   s = X @ W                     (tensor-core bf16x3 GEMM, unscaled)
//   h[c] = relu( dinv[c] * (dinv[c]*s[c] + sum_{r->c} dinv[r]*s[r]) + b )
// The dinv factors are applied during aggregation so the layer-1 GEMM has no
// dependency on the CSR/degree build -> it runs on a second stream overlapped
// with the prep chain (graph-capture fork/join via events).
// CSR build: histogram with rank capture (atomic returns each edge's slot),
// exclusive scan, then an atomic-free placement pass.
// ---------------------------------------------------------------------------

#define MAX_N 50000
#define MAX_E 640000

__device__ float g_dinv[MAX_N];        // rsqrt(in-degree incl. self loop)
__device__ float g_s  [MAX_N * 128];   // XW (gather source, unscaled)
__device__ float g_h  [MAX_N * 128];   // layer output
__device__ int   g_cnt[MAX_N];         // per-destination edge count
__device__ int   g_off[MAX_N + 1];     // CSR offsets
__device__ int   g_rank[MAX_E];        // per-edge rank within its destination
__device__ int   g_csr[MAX_E];         // source node per CSR slot
__device__ int   g_is64;               // edge_index dtype flag

// ----------------------- zero counts + dtype detect -------------------------
// int64 indices < 2^31 -> every odd 32-bit word is zero. int32 -> random.
__global__ void zero_detect_kernel(const int* __restrict__ ei, int n) {
    int i = blockIdx.x * blockDim.x + threadIdx.x;
    if (i < n) g_cnt[i] = 0;
    if (blockIdx.x == 0 && threadIdx.x < 32) {
        long long s = 0;
#pragma unroll
        for (int k = 0; k < 32; k++)
            s += (long long)__ldg(ei + 2 * (threadIdx.x * 32 + k) + 1);
#pragma unroll
        for (int o = 16; o > 0; o >>= 1)
            s += __shfl_down_sync(0xffffffffu, s, o);
        if (threadIdx.x == 0) g_is64 = (s == 0) ? 1 : 0;
    }
}

__device__ __forceinline__ void load_edge(const void* ei, int E, int e,
                                          int& r, int& c) {
    if (g_is64) {
        const long long* p = (const long long*)ei;
        r = (int)__ldg(p + e);
        c = (int)__ldg(p + E + e);
    } else {
        const int* p = (const int*)ei;
        r = __ldg(p + e);
        c = __ldg(p + E + e);
    }
}

// ------------------------------ CSR build ----------------------------------
// Histogram + rank capture: one atomic per edge, returns the edge's slot.
__global__ void hist_kernel(const void* __restrict__ ei, int E) {
    int e = blockIdx.x * blockDim.x + threadIdx.x;
    if (e >= E) return;
    int r, c; load_edge(ei, E, e, r, c);
    g_rank[e] = atomicAdd(&g_cnt[c], 1);
}

// Single-block exclusive scan over g_cnt -> g_off, plus dinv.
__global__ __launch_bounds__(1024) void scan_kernel(int n) {
    __shared__ int sh[32];
    __shared__ int carry_s;
    const int tid  = threadIdx.x;
    const int lane = tid & 31;
    const int warp = tid >> 5;
    if (tid == 0) carry_s = 0;
    __syncthreads();

    for (int base = 0; base < n; base += 1024) {
        const int i = base + tid;
        const int v = (i < n) ? g_cnt[i] : 0;
        int x = v;
#pragma unroll
        for (int o = 1; o < 32; o <<= 1) {
            int y = __shfl_up_sync(0xffffffffu, x, o);
            if (lane >= o) x += y;
        }
        if (lane == 31) sh[warp] = x;
        __syncthreads();
        if (tid < 32) {
            int w = sh[tid];
#pragma unroll
            for (int o = 1; o < 32; o <<= 1) {
                int y = __shfl_up_sync(0xffffffffu, w, o);
                if (tid >= o) w += y;
            }
            sh[tid] = w;
        }
        __syncthreads();
        const int pre  = (warp > 0) ? sh[warp - 1] : 0;
        const int incl = x + pre + carry_s;
        if (i < n) {
            g_off[i]  = incl - v;
            g_dinv[i] = rsqrtf((float)v + 1.0f);   // +1 = self loop
        }
        __syncthreads();
        if (tid == 1023) carry_s = incl;
        __syncthreads();
    }
    if (tid == 0) g_off[n] = carry_s;
}

// Atomic-free placement: pos = off[c] + rank[e].
__global__ void fillcsr_kernel(const void* __restrict__ ei, int E) {
    int e = blockIdx.x * blockDim.x + threadIdx.x;
    if (e >= E) return;
    int r, c; load_edge(ei, E, e, r, c);
    g_csr[g_off[c] + __ldg(&g_rank[e])] = r;
}

// --------------------------- bf16x3 tensor GEMM -----------------------------
__device__ __forceinline__ void pack2(float x, float y,
                                      uint32_t& h, uint32_t& l) {
    __nv_bfloat16 hx = __float2bfloat16_rn(x);
    __nv_bfloat16 hy = __float2bfloat16_rn(y);
    float rx = x - __bfloat162float(hx);
    float ry = y - __bfloat162float(hy);
    __nv_bfloat16 lx = __float2bfloat16_rn(rx);
    __nv_bfloat16 ly = __float2bfloat16_rn(ry);
    h = (uint32_t)*(uint16_t*)&hx | ((uint32_t)*(uint16_t*)&hy << 16);
    l = (uint32_t)*(uint16_t*)&lx | ((uint32_t)*(uint16_t*)&ly << 16);
}

#define MMA_BF16(c, a, b)                                                    \
    asm volatile("mma.sync.aligned.m16n8k16.row.col.f32.bf16.bf16.f32 "      \
                 "{%0,%1,%2,%3}, {%4,%5,%6,%7}, {%8,%9}, {%0,%1,%2,%3};"     \
                 : "+f"((c)[0]), "+f"((c)[1]), "+f"((c)[2]), "+f"((c)[3])    \
                 : "r"((a)[0]), "r"((a)[1]), "r"((a)[2]), "r"((a)[3]),       \
                   "r"((b)[0]), "r"((b)[1]))

// C[M,TN] = A[M,128] @ B[128,TN]. 128 x TN block tile, 256 threads (8 warps),
// full K=128 staged once in SMEM as packed-bf16 hi/lo.
// FINAL=false: g_s[row] = C[row] (raw)     FINAL=true: OUT = C + bias
template<int TN, bool FINAL>
__global__ __launch_bounds__(256, 1) void mma_gemm(
    const float* __restrict__ A, const float* __restrict__ B,
    const float* __restrict__ bias, float* __restrict__ OUT, int M)
{
    constexpr int WM  = (TN == 128) ? 2 : 4;
    constexpr int WN  = 8 / WM;
    constexpr int MT  = 128 / WM / 16;
    constexpr int NT  = TN / WN / 8;
    constexpr int RPW = 128 / WM;
    constexpr int CPW = TN / WN;
    constexpr int SW  = 68;

    extern __shared__ uint32_t smw[];
    uint32_t* As_hi = smw;
    uint32_t* As_lo = As_hi + 128 * SW;
    uint32_t* Bs_hi = As_lo + 128 * SW;
    uint32_t* Bs_lo = Bs_hi + TN * SW;

    const int tid    = threadIdx.x;
    const int warpId = tid >> 5;
    const int lane   = tid & 31;
    const int g      = lane >> 2;
    const int tg     = lane & 3;
    const int wm     = warpId % WM;
    const int wn     = warpId / WM;
    const int blockRow = blockIdx.x * 128;

    // ---- stage A: 128 rows x 128 k, split to hi/lo ----
#pragma unroll
    for (int it = 0; it < 16; it++) {
        const int s   = tid + it * 256;
        const int row = s >> 5;
        const int c4  = (s & 31) << 2;
        float4 v = make_float4(0.f, 0.f, 0.f, 0.f);
        if (blockRow + row < M)
            v = *(const float4*)(A + (size_t)(blockRow + row) * 128 + c4);
        uint32_t h0, l0, h1, l1;
        pack2(v.x, v.y, h0, l0);
        pack2(v.z, v.w, h1, l1);
        const int w = row * SW + ((s & 31) << 1);
        *(uint2*)&As_hi[w] = make_uint2(h0, h1);
        *(uint2*)&As_lo[w] = make_uint2(l0, l1);
    }
    // ---- stage B transposed: Bs[col][k] ----
#pragma unroll
    for (int it = 0; it < TN / 8; it++) {
        const int s   = tid + it * 256;
        const int col = s & (TN - 1);
        const int kb  = (s / TN) << 2;
        const float b0 = B[(size_t)(kb + 0) * TN + col];
        const float b1 = B[(size_t)(kb + 1) * TN + col];
        const float b2 = B[(size_t)(kb + 2) * TN + col];
        const float b3 = B[(size_t)(kb + 3) * TN + col];
        uint32_t h0, l0, h1, l1;
        pack2(b0, b1, h0, l0);
        pack2(b2, b3, h1, l1);
        const int w = col * SW + (kb >> 1);
        *(uint2*)&Bs_hi[w] = make_uint2(h0, h1);
        *(uint2*)&Bs_lo[w] = make_uint2(l0, l1);
    }
    __syncthreads();

    float acc[MT][NT][4];
#pragma unroll
    for (int mi = 0; mi < MT; mi++)
#pragma unroll
        for (int ni = 0; ni < NT; ni++)
#pragma unroll
            for (int q = 0; q < 4; q++) acc[mi][ni][q] = 0.0f;

#pragma unroll
    for (int kk = 0; kk < 8; kk++) {
        uint32_t ah[MT][4], al[MT][4];
#pragma unroll
        for (int mi = 0; mi < MT; mi++) {
            const int base = (wm * RPW + mi * 16 + g) * SW + kk * 8 + tg;
            ah[mi][0] = As_hi[base];
            ah[mi][1] = As_hi[base + 8 * SW];
            ah[mi][2] = As_hi[base + 4];
            ah[mi][3] = As_hi[base + 8 * SW + 4];
            al[mi][0] = As_lo[base];
            al[mi][1] = As_lo[base + 8 * SW];
            al[mi][2] = As_lo[base + 4];
            al[mi][3] = As_lo[base + 8 * SW + 4];
        }
        uint32_t bh[NT][2], bl[NT][2];
#pragma unroll
        for (int ni = 0; ni < NT; ni++) {
            const int base = (wn * CPW + ni * 8 + g) * SW + kk * 8 + tg;
            bh[ni][0] = Bs_hi[base];
            bh[ni][1] = Bs_hi[base + 4];
            bl[ni][0] = Bs_lo[base];
            bl[ni][1] = Bs_lo[base + 4];
        }
#pragma unroll
        for (int mi = 0; mi < MT; mi++)
#pragma unroll
            for (int ni = 0; ni < NT; ni++) {
                MMA_BF16(acc[mi][ni], ah[mi], bh[ni]);
                MMA_BF16(acc[mi][ni], al[mi], bh[ni]);
                MMA_BF16(acc[mi][ni], ah[mi], bl[ni]);
            }
    }

    // ---- epilogue ----
#pragma unroll
    for (int mi = 0; mi < MT; mi++) {
        const int rbase = blockRow + wm * RPW + mi * 16;
        const int r0 = rbase + g;
        const int r1 = rbase + g + 8;
#pragma unroll
        for (int ni = 0; ni < NT; ni++) {
            const int col = wn * CPW + ni * 8 + tg * 2;
            if (FINAL) {
                const float2 bb = __ldg((const float2*)(bias + col));
                if (r0 < M)
                    *(float2*)(OUT + (size_t)r0 * TN + col) =
                        make_float2(acc[mi][ni][0] + bb.x, acc[mi][ni][1] + bb.y);
                if (r1 < M)
                    *(float2*)(OUT + (size_t)r1 * TN + col) =
                        make_float2(acc[mi][ni][2] + bb.x, acc[mi][ni][3] + bb.y);
            } else {
                if (r0 < M)
                    *(float2*)(g_s + (size_t)r0 * TN + col) =
                        make_float2(acc[mi][ni][0], acc[mi][ni][1]);
                if (r1 < M)
                    *(float2*)(g_s + (size_t)r1 * TN + col) =
                        make_float2(acc[mi][ni][2], acc[mi][ni][3]);
            }
        }
    }
}

// --------------------------- neighbor aggregation ---------------------------
// One warp per node; dinv applied per-gathered-row (s is unscaled XW).
__global__ __launch_bounds__(256) void aggregate_kernel(
    const float* __restrict__ bias, int n)
{
    const int node = (blockIdx.x * 256 + threadIdx.x) >> 5;
    const int lane = threadIdx.x & 31;
    if (node >= n) return;

    const float dself = __ldg(&g_dinv[node]);
    const float4 sv = __ldg((const float4*)(g_s + (size_t)node * 128) + lane);
    float4 acc = make_float4(dself * sv.x, dself * sv.y,
                             dself * sv.z, dself * sv.w);   // self term
    int i = g_off[node];
    const int end = g_off[node + 1];

    for (; i + 4 <= end; i += 4) {
        const int r0 = __ldg(&g_csr[i]);
        const int r1 = __ldg(&g_csr[i + 1]);
        const int r2 = __ldg(&g_csr[i + 2]);
        const int r3 = __ldg(&g_csr[i + 3]);
        const float d0 = __ldg(&g_dinv[r0]);
        const float d1 = __ldg(&g_dinv[r1]);
        const float d2 = __ldg(&g_dinv[r2]);
        const float d3 = __ldg(&g_dinv[r3]);
        const float4 v0 = __ldg((const float4*)(g_s + (size_t)r0 * 128) + lane);
        const float4 v1 = __ldg((const float4*)(g_s + (size_t)r1 * 128) + lane);
        const float4 v2 = __ldg((const float4*)(g_s + (size_t)r2 * 128) + lane);
        const float4 v3 = __ldg((const float4*)(g_s + (size_t)r3 * 128) + lane);
        acc.x = fmaf(d0, v0.x, fmaf(d1, v1.x, fmaf(d2, v2.x, fmaf(d3, v3.x, acc.x))));
        acc.y = fmaf(d0, v0.y, fmaf(d1, v1.y, fmaf(d2, v2.y, fmaf(d3, v3.y, acc.y))));
        acc.z = fmaf(d0, v0.z, fmaf(d1, v1.z, fmaf(d2, v2.z, fmaf(d3, v3.z, acc.z))));
        acc.w = fmaf(d0, v0.w, fmaf(d1, v1.w, fmaf(d2, v2.w, fmaf(d3, v3.w, acc.w))));
    }
    for (; i < end; i++) {
        const int r = __ldg(&g_csr[i]);
        const float d = __ldg(&g_dinv[r]);
        const float4 v = __ldg((const float4*)(g_s + (size_t)r * 128) + lane);
        acc.x = fmaf(d, v.x, acc.x);
        acc.y = fmaf(d, v.y, acc.y);
        acc.z = fmaf(d, v.z, acc.z);
        acc.w = fmaf(d, v.w, acc.w);
    }

    const float4 b = __ldg((const float4*)bias + lane);
    float4 r;
    r.x = fmaxf(fmaf(dself, acc.x, b.x), 0.f);
    r.y = fmaxf(fmaf(dself, acc.y, b.y), 0.f);
    r.z = fmaxf(fmaf(dself, acc.z, b.z), 0.f);
    r.w = fmaxf(fmaf(dself, acc.w, b.w), 0.f);
    *((float4*)(g_h + (size_t)node * 128) + lane) = r;
}

// ------------------------------- launch -------------------------------------
extern "C" void kernel_launch(void* const* d_in, const int* in_sizes, int n_in,
                              void* d_out, int out_size) {
    const float* x  = (const float*)d_in[0];
    const void*  ei =               d_in[1];
    const float* W1 = (const float*)d_in[2];
    const float* b1 = (const float*)d_in[3];
    const float* W2 = (const float*)d_in[4];
    const float* b2 = (const float*)d_in[5];
    const float* Wl = (const float*)d_in[6];
    const float* bl = (const float*)d_in[7];
    float* out = (float*)d_out;

    const int n = in_sizes[0] / 128;   // 50000
    const int E = in_sizes[1] / 2;     // 640000

    float* h_dev = nullptr;  cudaGetSymbolAddress((void**)&h_dev, g_h);

    const int smem128 = (128 * 68 * 2 + 128 * 68 * 2) * 4;   // 139264 B
    const int smem64  = (128 * 68 * 2 +  64 * 68 * 2) * 4;   // 104448 B

    // One-time setup on the first (non-captured) correctness call: func
    // attributes plus a side stream + fork/join events for graph-level overlap.
    static cudaStream_t s1 = nullptr;
    static cudaEvent_t evFork = nullptr, evJoin = nullptr;
    if (s1 == nullptr) {
        cudaFuncSetAttribute(mma_gemm<128, false>,
                             cudaFuncAttributeMaxDynamicSharedMemorySize, smem128);
        cudaFuncSetAttribute(mma_gemm<64, true>,
                             cudaFuncAttributeMaxDynamicSharedMemorySize, smem64);
        cudaStreamCreateWithFlags(&s1, cudaStreamNonBlocking);
        cudaEventCreateWithFlags(&evFork, cudaEventDisableTiming);
        cudaEventCreateWithFlags(&evJoin, cudaEventDisableTiming);
    }

    const int eB = (E + 255) / 256;
    const int nB = (n + 255) / 256;
    const int gemmBlocks = (n + 127) / 128;
    const int aggBlocks  = (n * 32 + 255) / 256;

    // ---- fork: layer-1 GEMM (independent of graph prep) on side stream ----
    cudaEventRecord(evFork, 0);
    cudaStreamWaitEvent(s1, evFork, 0);
    mma_gemm<128, false><<<gemmBlocks, 256, smem128, s1>>>(x, W1, nullptr, nullptr, n);
    cudaEventRecord(evJoin, s1);

    // ---- CSR + normalization build on the main stream (overlapped) ----
    zero_detect_kernel<<<nB, 256>>>((const int*)ei, n);
    hist_kernel<<<eB, 256>>>(ei, E);
    scan_kernel<<<1, 1024>>>(n);
    fillcsr_kernel<<<eB, 256>>>(ei, E);

    // ---- join, then the serial tail ----
    cudaStreamWaitEvent(0, evJoin, 0);
    aggregate_kernel<<<aggBlocks, 256>>>(b1, n);

    mma_gemm<128, false><<<gemmBlocks, 256, smem128>>>(h_dev, W2, nullptr, nullptr, n);
    aggregate_kernel<<<aggBlocks, 256>>>(b2, n);

    mma_gemm<64, true><<<gemmBlocks, 256, smem64>>>(h_dev, Wl, bl, out, n);
}

// round 14
// speedup vs baseline: 2.2755x; 1.2199x over previous
#include <cuda_runtime.h>
#include <cuda_bf16.h>
#include <cstdint>

// ---------------------------------------------------------------------------
// TrivialGNN: 3-layer GCN.
// Per GCN layer:
//   s = X @ W                     (tensor-core bf16x3 GEMM, unscaled)
//   h[c] = relu( dinv[c] * (dinv[c]*s[c] + sum_{r->c} dinv[r]*s[r]) + b )
// dinv applied during aggregation so the layer-1 GEMM is independent of the
// CSR build and overlaps it on a second stream (graph fork/join via events).
// CSR build: histogram with rank capture, MULTI-BLOCK 3-phase exclusive scan
// (block reduce -> scan of block sums -> block scan + offset), atomic-free
// placement.
// ---------------------------------------------------------------------------

#define MAX_N 50000
#define MAX_E 640000
#define SCAN_B 256                     // scan block size
#define MAX_SB 256                     // max scan blocks (n <= 65536)

__device__ float g_dinv[MAX_N];        // rsqrt(in-degree incl. self loop)
__device__ float g_s  [MAX_N * 128];   // XW (gather source, unscaled)
__device__ float g_h  [MAX_N * 128];   // layer output
__device__ int   g_cnt[MAX_N];         // per-destination edge count
__device__ int   g_off[MAX_N + 1];     // CSR offsets
__device__ int   g_rank[MAX_E];        // per-edge rank within its destination
__device__ int   g_csr[MAX_E];         // source node per CSR slot
__device__ int   g_bsum[MAX_SB];       // per-block count sums
__device__ int   g_boff[MAX_SB];       // per-block scan offsets
__device__ int   g_is64;               // edge_index dtype flag

// ----------------------- zero counts + dtype detect -------------------------
__global__ void zero_detect_kernel(const int* __restrict__ ei, int n) {
    int i = blockIdx.x * blockDim.x + threadIdx.x;
    if (i < n) g_cnt[i] = 0;
    if (blockIdx.x == 0 && threadIdx.x < 32) {
        long long s = 0;
#pragma unroll
        for (int k = 0; k < 32; k++)
            s += (long long)__ldg(ei + 2 * (threadIdx.x * 32 + k) + 1);
#pragma unroll
        for (int o = 16; o > 0; o >>= 1)
            s += __shfl_down_sync(0xffffffffu, s, o);
        if (threadIdx.x == 0) g_is64 = (s == 0) ? 1 : 0;
    }
}

__device__ __forceinline__ void load_edge(const void* ei, int E, int e,
                                          int& r, int& c) {
    if (g_is64) {
        const long long* p = (const long long*)ei;
        r = (int)__ldg(p + e);
        c = (int)__ldg(p + E + e);
    } else {
        const int* p = (const int*)ei;
        r = __ldg(p + e);
        c = __ldg(p + E + e);
    }
}

// ------------------------------ CSR build ----------------------------------
// Histogram + rank capture: one atomic per edge, returns the edge's slot.
__global__ void hist_kernel(const void* __restrict__ ei, int E) {
    int e = blockIdx.x * blockDim.x + threadIdx.x;
    if (e >= E) return;
    int r, c; load_edge(ei, E, e, r, c);
    g_rank[e] = atomicAdd(&g_cnt[c], 1);
}

// ---- scan phase 1: per-block reduction of counts (+ dinv on the way) ------
__global__ __launch_bounds__(SCAN_B) void scan_blocksum(int n) {
    const int tid  = threadIdx.x;
    const int i    = blockIdx.x * SCAN_B + tid;
    const int lane = tid & 31;
    const int warp = tid >> 5;
    int v = (i < n) ? g_cnt[i] : 0;
    if (i < n) g_dinv[i] = rsqrtf((float)v + 1.0f);   // +1 = self loop
    int s = v;
#pragma unroll
    for (int o = 16; o > 0; o >>= 1) s += __shfl_down_sync(0xffffffffu, s, o);
    __shared__ int sh[SCAN_B / 32];
    if (lane == 0) sh[warp] = s;
    __syncthreads();
    if (tid == 0) {
        int t = 0;
#pragma unroll
        for (int w = 0; w < SCAN_B / 32; w++) t += sh[w];
        g_bsum[blockIdx.x] = t;
    }
}

// ---- scan phase 2: one block scans the block sums --------------------------
__global__ __launch_bounds__(256) void scan_tops(int nb, int n) {
    const int tid  = threadIdx.x;
    const int lane = tid & 31;
    const int warp = tid >> 5;
    __shared__ int sh[8];
    int v = (tid < nb) ? g_bsum[tid] : 0;
    int x = v;
#pragma unroll
    for (int o = 1; o < 32; o <<= 1) {
        int y = __shfl_up_sync(0xffffffffu, x, o);
        if (lane >= o) x += y;
    }
    if (lane == 31) sh[warp] = x;
    __syncthreads();
    if (tid < 8) {
        int w = sh[tid];
#pragma unroll
        for (int o = 1; o < 8; o <<= 1) {
            int y = __shfl_up_sync(0xffu, w, o);
            if (tid >= o) w += y;
        }
        sh[tid] = w;
    }
    __syncthreads();
    const int incl = x + ((warp > 0) ? sh[warp - 1] : 0);
    if (tid < nb) g_boff[tid] = incl - v;
    if (tid == 255) g_off[n] = incl;   // grand total (tail lanes hold zeros)
}

// ---- scan phase 3: block-local exclusive scan + block offset ----------------
__global__ __launch_bounds__(SCAN_B) void scan_final(int n) {
    const int tid  = threadIdx.x;
    const int i    = blockIdx.x * SCAN_B + tid;
    const int lane = tid & 31;
    const int warp = tid >> 5;
    __shared__ int sh[SCAN_B / 32];
    const int v = (i < n) ? g_cnt[i] : 0;
    int x = v;
#pragma unroll
    for (int o = 1; o < 32; o <<= 1) {
        int y = __shfl_up_sync(0xffffffffu, x, o);
        if (lane >= o) x += y;
    }
    if (lane == 31) sh[warp] = x;
    __syncthreads();
    if (tid < SCAN_B / 32) {
        int w = sh[tid];
#pragma unroll
        for (int o = 1; o < SCAN_B / 32; o <<= 1) {
            int y = __shfl_up_sync((1u << (SCAN_B / 32)) - 1u, w, o);
            if (tid >= o) w += y;
        }
        sh[tid] = w;
    }
    __syncthreads();
    const int incl = x + ((warp > 0) ? sh[warp - 1] : 0);
    if (i < n) g_off[i] = g_boff[blockIdx.x] + incl - v;
}

// Atomic-free placement: pos = off[c] + rank[e].
__global__ void fillcsr_kernel(const void* __restrict__ ei, int E) {
    int e = blockIdx.x * blockDim.x + threadIdx.x;
    if (e >= E) return;
    int r, c; load_edge(ei, E, e, r, c);
    g_csr[g_off[c] + __ldg(&g_rank[e])] = r;
}

// --------------------------- bf16x3 tensor GEMM -----------------------------
__device__ __forceinline__ void pack2(float x, float y,
                                      uint32_t& h, uint32_t& l) {
    __nv_bfloat16 hx = __float2bfloat16_rn(x);
    __nv_bfloat16 hy = __float2bfloat16_rn(y);
    float rx = x - __bfloat162float(hx);
    float ry = y - __bfloat162float(hy);
    __nv_bfloat16 lx = __float2bfloat16_rn(rx);
    __nv_bfloat16 ly = __float2bfloat16_rn(ry);
    h = (uint32_t)*(uint16_t*)&hx | ((uint32_t)*(uint16_t*)&hy << 16);
    l = (uint32_t)*(uint16_t*)&lx | ((uint32_t)*(uint16_t*)&ly << 16);
}

#define MMA_BF16(c, a, b)                                                    \
    asm volatile("mma.sync.aligned.m16n8k16.row.col.f32.bf16.bf16.f32 "      \
                 "{%0,%1,%2,%3}, {%4,%5,%6,%7}, {%8,%9}, {%0,%1,%2,%3};"     \
                 : "+f"((c)[0]), "+f"((c)[1]), "+f"((c)[2]), "+f"((c)[3])    \
                 : "r"((a)[0]), "r"((a)[1]), "r"((a)[2]), "r"((a)[3]),       \
                   "r"((b)[0]), "r"((b)[1]))

// C[M,TN] = A[M,128] @ B[128,TN]. 128 x TN block tile, 256 threads (8 warps),
// full K=128 staged once in SMEM as packed-bf16 hi/lo.
// FINAL=false: g_s[row] = C[row]      FINAL=true: OUT = C + bias
template<int TN, bool FINAL>
__global__ __launch_bounds__(256, 1) void mma_gemm(
    const float* __restrict__ A, const float* __restrict__ B,
    const float* __restrict__ bias, float* __restrict__ OUT, int M)
{
    constexpr int WM  = (TN == 128) ? 2 : 4;
    constexpr int WN  = 8 / WM;
    constexpr int MT  = 128 / WM / 16;
    constexpr int NT  = TN / WN / 8;
    constexpr int RPW = 128 / WM;
    constexpr int CPW = TN / WN;
    constexpr int SW  = 68;

    extern __shared__ uint32_t smw[];
    uint32_t* As_hi = smw;
    uint32_t* As_lo = As_hi + 128 * SW;
    uint32_t* Bs_hi = As_lo + 128 * SW;
    uint32_t* Bs_lo = Bs_hi + TN * SW;

    const int tid    = threadIdx.x;
    const int warpId = tid >> 5;
    const int lane   = tid & 31;
    const int g      = lane >> 2;
    const int tg     = lane & 3;
    const int wm     = warpId % WM;
    const int wn     = warpId / WM;
    const int blockRow = blockIdx.x * 128;

#pragma unroll
    for (int it = 0; it < 16; it++) {
        const int s   = tid + it * 256;
        const int row = s >> 5;
        const int c4  = (s & 31) << 2;
        float4 v = make_float4(0.f, 0.f, 0.f, 0.f);
        if (blockRow + row < M)
            v = *(const float4*)(A + (size_t)(blockRow + row) * 128 + c4);
        uint32_t h0, l0, h1, l1;
        pack2(v.x, v.y, h0, l0);
        pack2(v.z, v.w, h1, l1);
        const int w = row * SW + ((s & 31) << 1);
        *(uint2*)&As_hi[w] = make_uint2(h0, h1);
        *(uint2*)&As_lo[w] = make_uint2(l0, l1);
    }
#pragma unroll
    for (int it = 0; it < TN / 8; it++) {
        const int s   = tid + it * 256;
        const int col = s & (TN - 1);
        const int kb  = (s / TN) << 2;
        const float b0 = B[(size_t)(kb + 0) * TN + col];
        const float b1 = B[(size_t)(kb + 1) * TN + col];
        const float b2 = B[(size_t)(kb + 2) * TN + col];
        const float b3 = B[(size_t)(kb + 3) * TN + col];
        uint32_t h0, l0, h1, l1;
        pack2(b0, b1, h0, l0);
        pack2(b2, b3, h1, l1);
        const int w = col * SW + (kb >> 1);
        *(uint2*)&Bs_hi[w] = make_uint2(h0, h1);
        *(uint2*)&Bs_lo[w] = make_uint2(l0, l1);
    }
    __syncthreads();

    float acc[MT][NT][4];
#pragma unroll
    for (int mi = 0; mi < MT; mi++)
#pragma unroll
        for (int ni = 0; ni < NT; ni++)
#pragma unroll
            for (int q = 0; q < 4; q++) acc[mi][ni][q] = 0.0f;

#pragma unroll
    for (int kk = 0; kk < 8; kk++) {
        uint32_t ah[MT][4], al[MT][4];
#pragma unroll
        for (int mi = 0; mi < MT; mi++) {
            const int base = (wm * RPW + mi * 16 + g) * SW + kk * 8 + tg;
            ah[mi][0] = As_hi[base];
            ah[mi][1] = As_hi[base + 8 * SW];
            ah[mi][2] = As_hi[base + 4];
            ah[mi][3] = As_hi[base + 8 * SW + 4];
            al[mi][0] = As_lo[base];
            al[mi][1] = As_lo[base + 8 * SW];
            al[mi][2] = As_lo[base + 4];
            al[mi][3] = As_lo[base + 8 * SW + 4];
        }
        uint32_t bh[NT][2], bl[NT][2];
#pragma unroll
        for (int ni = 0; ni < NT; ni++) {
            const int base = (wn * CPW + ni * 8 + g) * SW + kk * 8 + tg;
            bh[ni][0] = Bs_hi[base];
            bh[ni][1] = Bs_hi[base + 4];
            bl[ni][0] = Bs_lo[base];
            bl[ni][1] = Bs_lo[base + 4];
        }
#pragma unroll
        for (int mi = 0; mi < MT; mi++)
#pragma unroll
            for (int ni = 0; ni < NT; ni++) {
                MMA_BF16(acc[mi][ni], ah[mi], bh[ni]);
                MMA_BF16(acc[mi][ni], al[mi], bh[ni]);
                MMA_BF16(acc[mi][ni], ah[mi], bl[ni]);
            }
    }

#pragma unroll
    for (int mi = 0; mi < MT; mi++) {
        const int rbase = blockRow + wm * RPW + mi * 16;
        const int r0 = rbase + g;
        const int r1 = rbase + g + 8;
#pragma unroll
        for (int ni = 0; ni < NT; ni++) {
            const int col = wn * CPW + ni * 8 + tg * 2;
            if (FINAL) {
                const float2 bb = __ldg((const float2*)(bias + col));
                if (r0 < M)
                    *(float2*)(OUT + (size_t)r0 * TN + col) =
                        make_float2(acc[mi][ni][0] + bb.x, acc[mi][ni][1] + bb.y);
                if (r1 < M)
                    *(float2*)(OUT + (size_t)r1 * TN + col) =
                        make_float2(acc[mi][ni][2] + bb.x, acc[mi][ni][3] + bb.y);
            } else {
                if (r0 < M)
                    *(float2*)(g_s + (size_t)r0 * TN + col) =
                        make_float2(acc[mi][ni][0], acc[mi][ni][1]);
                if (r1 < M)
                    *(float2*)(g_s + (size_t)r1 * TN + col) =
                        make_float2(acc[mi][ni][2], acc[mi][ni][3]);
            }
        }
    }
}

// --------------------------- neighbor aggregation ---------------------------
__global__ __launch_bounds__(256) void aggregate_kernel(
    const float* __restrict__ bias, int n)
{
    const int node = (blockIdx.x * 256 + threadIdx.x) >> 5;
    const int lane = threadIdx.x & 31;
    if (node >= n) return;

    const float dself = __ldg(&g_dinv[node]);
    const float4 sv = __ldg((const float4*)(g_s + (size_t)node * 128) + lane);
    float4 acc = make_float4(dself * sv.x, dself * sv.y,
                             dself * sv.z, dself * sv.w);
    int i = g_off[node];
    const int end = g_off[node + 1];

    for (; i + 4 <= end; i += 4) {
        const int r0 = __ldg(&g_csr[i]);
        const int r1 = __ldg(&g_csr[i + 1]);
        const int r2 = __ldg(&g_csr[i + 2]);
        const int r3 = __ldg(&g_csr[i + 3]);
        const float d0 = __ldg(&g_dinv[r0]);
        const float d1 = __ldg(&g_dinv[r1]);
        const float d2 = __ldg(&g_dinv[r2]);
        const float d3 = __ldg(&g_dinv[r3]);
        const float4 v0 = __ldg((const float4*)(g_s + (size_t)r0 * 128) + lane);
        const float4 v1 = __ldg((const float4*)(g_s + (size_t)r1 * 128) + lane);
        const float4 v2 = __ldg((const float4*)(g_s + (size_t)r2 * 128) + lane);
        const float4 v3 = __ldg((const float4*)(g_s + (size_t)r3 * 128) + lane);
        acc.x = fmaf(d0, v0.x, fmaf(d1, v1.x, fmaf(d2, v2.x, fmaf(d3, v3.x, acc.x))));
        acc.y = fmaf(d0, v0.y, fmaf(d1, v1.y, fmaf(d2, v2.y, fmaf(d3, v3.y, acc.y))));
        acc.z = fmaf(d0, v0.z, fmaf(d1, v1.z, fmaf(d2, v2.z, fmaf(d3, v3.z, acc.z))));
        acc.w = fmaf(d0, v0.w, fmaf(d1, v1.w, fmaf(d2, v2.w, fmaf(d3, v3.w, acc.w))));
    }
    for (; i < end; i++) {
        const int r = __ldg(&g_csr[i]);
        const float d = __ldg(&g_dinv[r]);
        const float4 v = __ldg((const float4*)(g_s + (size_t)r * 128) + lane);
        acc.x = fmaf(d, v.x, acc.x);
        acc.y = fmaf(d, v.y, acc.y);
        acc.z = fmaf(d, v.z, acc.z);
        acc.w = fmaf(d, v.w, acc.w);
    }

    const float4 b = __ldg((const float4*)bias + lane);
    float4 r;
    r.x = fmaxf(fmaf(dself, acc.x, b.x), 0.f);
    r.y = fmaxf(fmaf(dself, acc.y, b.y), 0.f);
    r.z = fmaxf(fmaf(dself, acc.z, b.z), 0.f);
    r.w = fmaxf(fmaf(dself, acc.w, b.w), 0.f);
    *((float4*)(g_h + (size_t)node * 128) + lane) = r;
}

// ------------------------------- launch -------------------------------------
extern "C" void kernel_launch(void* const* d_in, const int* in_sizes, int n_in,
                              void* d_out, int out_size) {
    const float* x  = (const float*)d_in[0];
    const void*  ei =               d_in[1];
    const float* W1 = (const float*)d_in[2];
    const float* b1 = (const float*)d_in[3];
    const float* W2 = (const float*)d_in[4];
    const float* b2 = (const float*)d_in[5];
    const float* Wl = (const float*)d_in[6];
    const float* bl = (const float*)d_in[7];
    float* out = (float*)d_out;

    const int n = in_sizes[0] / 128;   // 50000
    const int E = in_sizes[1] / 2;     // 640000

    float* h_dev = nullptr;  cudaGetSymbolAddress((void**)&h_dev, g_h);

    const int smem128 = (128 * 68 * 2 + 128 * 68 * 2) * 4;   // 139264 B
    const int smem64  = (128 * 68 * 2 +  64 * 68 * 2) * 4;   // 104448 B

    static cudaStream_t s1 = nullptr;
    static cudaEvent_t evFork = nullptr, evJoin = nullptr;
    if (s1 == nullptr) {
        cudaFuncSetAttribute(mma_gemm<128, false>,
                             cudaFuncAttributeMaxDynamicSharedMemorySize, smem128);
        cudaFuncSetAttribute(mma_gemm<64, true>,
                             cudaFuncAttributeMaxDynamicSharedMemorySize, smem64);
        cudaStreamCreateWithFlags(&s1, cudaStreamNonBlocking);
        cudaEventCreateWithFlags(&evFork, cudaEventDisableTiming);
        cudaEventCreateWithFlags(&evJoin, cudaEventDisableTiming);
    }

    const int eB = (E + 255) / 256;
    const int nB = (n + 255) / 256;
    const int sB = (n + SCAN_B - 1) / SCAN_B;    // scan blocks (196)
    const int gemmBlocks = (n + 127) / 128;
    const int aggBlocks  = (n * 32 + 255) / 256;

    // ---- fork: layer-1 GEMM (independent of graph prep) on side stream ----
    cudaEventRecord(evFork, 0);
    cudaStreamWaitEvent(s1, evFork, 0);
    mma_gemm<128, false><<<gemmBlocks, 256, smem128, s1>>>(x, W1, nullptr, nullptr, n);
    cudaEventRecord(evJoin, s1);

    // ---- CSR + normalization build on the main stream (overlapped) ----
    zero_detect_kernel<<<nB, 256>>>((const int*)ei, n);
    hist_kernel<<<eB, 256>>>(ei, E);
    scan_blocksum<<<sB, SCAN_B>>>(n);
    scan_tops<<<1, 256>>>(sB, n);
    scan_final<<<sB, SCAN_B>>>(n);
    fillcsr_kernel<<<eB, 256>>>(ei, E);

    // ---- join, then the serial tail ----
    cudaStreamWaitEvent(0, evJoin, 0);
    aggregate_kernel<<<aggBlocks, 256>>>(b1, n);

    mma_gemm<128, false><<<gemmBlocks, 256, smem128>>>(h_dev, W2, nullptr, nullptr, n);
    aggregate_kernel<<<aggBlocks, 256>>>(b2, n);

    mma_gemm<64, true><<<gemmBlocks, 256, smem64>>>(h_dev, Wl, bl, out, n);
}

// round 15
// speedup vs baseline: 2.2927x; 1.0076x over previous
#include <cuda_runtime.h>
#include <cuda_bf16.h>
#include <cstdint>

// ---------------------------------------------------------------------------
// TrivialGNN: 3-layer GCN.
// Per GCN layer:
//   s = X @ W                     (tensor-core bf16x3 GEMM, unscaled)
//   h[c] = relu( dinv[c] * (dinv[c]*s[c] + sum_{r->c} dinv[r]*s[r]) + b )
// dinv applied during aggregation so the layer-1 GEMM is independent of the
// CSR build and overlaps it on a second stream (graph fork/join via events).
// CSR build: histogram with rank capture, MULTI-BLOCK 3-phase exclusive scan
// (block reduce -> scan of block sums -> block scan + offset), atomic-free
// placement.
// ---------------------------------------------------------------------------

#define MAX_N 50000
#define MAX_E 640000
#define SCAN_B 256                     // scan block size
#define MAX_SB 256                     // max scan blocks (n <= 65536)

__device__ float g_dinv[MAX_N];        // rsqrt(in-degree incl. self loop)
__device__ float g_s  [MAX_N * 128];   // XW (gather source, unscaled)
__device__ float g_h  [MAX_N * 128];   // layer output
__device__ int   g_cnt[MAX_N];         // per-destination edge count
__device__ int   g_off[MAX_N + 1];     // CSR offsets
__device__ int   g_rank[MAX_E];        // per-edge rank within its destination
__device__ int   g_csr[MAX_E];         // source node per CSR slot
__device__ int   g_bsum[MAX_SB];       // per-block count sums
__device__ int   g_boff[MAX_SB];       // per-block scan offsets
__device__ int   g_is64;               // edge_index dtype flag

// ----------------------- zero counts + dtype detect -------------------------
__global__ void zero_detect_kernel(const int* __restrict__ ei, int n) {
    int i = blockIdx.x * blockDim.x + threadIdx.x;
    if (i < n) g_cnt[i] = 0;
    if (blockIdx.x == 0 && threadIdx.x < 32) {
        long long s = 0;
#pragma unroll
        for (int k = 0; k < 32; k++)
            s += (long long)__ldg(ei + 2 * (threadIdx.x * 32 + k) + 1);
#pragma unroll
        for (int o = 16; o > 0; o >>= 1)
            s += __shfl_down_sync(0xffffffffu, s, o);
        if (threadIdx.x == 0) g_is64 = (s == 0) ? 1 : 0;
    }
}

__device__ __forceinline__ void load_edge(const void* ei, int E, int e,
                                          int& r, int& c) {
    if (g_is64) {
        const long long* p = (const long long*)ei;
        r = (int)__ldg(p + e);
        c = (int)__ldg(p + E + e);
    } else {
        const int* p = (const int*)ei;
        r = __ldg(p + e);
        c = __ldg(p + E + e);
    }
}

// ------------------------------ CSR build ----------------------------------
// Histogram + rank capture: one atomic per edge, returns the edge's slot.
__global__ void hist_kernel(const void* __restrict__ ei, int E) {
    int e = blockIdx.x * blockDim.x + threadIdx.x;
    if (e >= E) return;
    int r, c; load_edge(ei, E, e, r, c);
    g_rank[e] = atomicAdd(&g_cnt[c], 1);
}

// ---- scan phase 1: per-block reduction of counts (+ dinv on the way) ------
__global__ __launch_bounds__(SCAN_B) void scan_blocksum(int n) {
    const int tid  = threadIdx.x;
    const int i    = blockIdx.x * SCAN_B + tid;
    const int lane = tid & 31;
    const int warp = tid >> 5;
    int v = (i < n) ? g_cnt[i] : 0;
    if (i < n) g_dinv[i] = rsqrtf((float)v + 1.0f);   // +1 = self loop
    int s = v;
#pragma unroll
    for (int o = 16; o > 0; o >>= 1) s += __shfl_down_sync(0xffffffffu, s, o);
    __shared__ int sh[SCAN_B / 32];
    if (lane == 0) sh[warp] = s;
    __syncthreads();
    if (tid == 0) {
        int t = 0;
#pragma unroll
        for (int w = 0; w < SCAN_B / 32; w++) t += sh[w];
        g_bsum[blockIdx.x] = t;
    }
}

// ---- scan phase 2: one block scans the block sums --------------------------
__global__ __launch_bounds__(256) void scan_tops(int nb, int n) {
    const int tid  = threadIdx.x;
    const int lane = tid & 31;
    const int warp = tid >> 5;
    __shared__ int sh[8];
    int v = (tid < nb) ? g_bsum[tid] : 0;
    int x = v;
#pragma unroll
    for (int o = 1; o < 32; o <<= 1) {
        int y = __shfl_up_sync(0xffffffffu, x, o);
        if (lane >= o) x += y;
    }
    if (lane == 31) sh[warp] = x;
    __syncthreads();
    if (tid < 8) {
        int w = sh[tid];
#pragma unroll
        for (int o = 1; o < 8; o <<= 1) {
            int y = __shfl_up_sync(0xffu, w, o);
            if (tid >= o) w += y;
        }
        sh[tid] = w;
    }
    __syncthreads();
    const int incl = x + ((warp > 0) ? sh[warp - 1] : 0);
    if (tid < nb) g_boff[tid] = incl - v;
    if (tid == 255) g_off[n] = incl;   // grand total (tail lanes hold zeros)
}

// ---- scan phase 3: block-local exclusive scan + block offset ----------------
__global__ __launch_bounds__(SCAN_B) void scan_final(int n) {
    const int tid  = threadIdx.x;
    const int i    = blockIdx.x * SCAN_B + tid;
    const int lane = tid & 31;
    const int warp = tid >> 5;
    __shared__ int sh[SCAN_B / 32];
    const int v = (i < n) ? g_cnt[i] : 0;
    int x = v;
#pragma unroll
    for (int o = 1; o < 32; o <<= 1) {
        int y = __shfl_up_sync(0xffffffffu, x, o);
        if (lane >= o) x += y;
    }
    if (lane == 31) sh[warp] = x;
    __syncthreads();
    if (tid < SCAN_B / 32) {
        int w = sh[tid];
#pragma unroll
        for (int o = 1; o < SCAN_B / 32; o <<= 1) {
            int y = __shfl_up_sync((1u << (SCAN_B / 32)) - 1u, w, o);
            if (tid >= o) w += y;
        }
        sh[tid] = w;
    }
    __syncthreads();
    const int incl = x + ((warp > 0) ? sh[warp - 1] : 0);
    if (i < n) g_off[i] = g_boff[blockIdx.x] + incl - v;
}

// Atomic-free placement: pos = off[c] + rank[e].
__global__ void fillcsr_kernel(const void* __restrict__ ei, int E) {
    int e = blockIdx.x * blockDim.x + threadIdx.x;
    if (e >= E) return;
    int r, c; load_edge(ei, E, e, r, c);
    g_csr[g_off[c] + __ldg(&g_rank[e])] = r;
}

// --------------------------- bf16x3 tensor GEMM -----------------------------
__device__ __forceinline__ void pack2(float x, float y,
                                      uint32_t& h, uint32_t& l) {
    __nv_bfloat16 hx = __float2bfloat16_rn(x);
    __nv_bfloat16 hy = __float2bfloat16_rn(y);
    float rx = x - __bfloat162float(hx);
    float ry = y - __bfloat162float(hy);
    __nv_bfloat16 lx = __float2bfloat16_rn(rx);
    __nv_bfloat16 ly = __float2bfloat16_rn(ry);
    h = (uint32_t)*(uint16_t*)&hx | ((uint32_t)*(uint16_t*)&hy << 16);
    l = (uint32_t)*(uint16_t*)&lx | ((uint32_t)*(uint16_t*)&ly << 16);
}

#define MMA_BF16(c, a, b)                                                    \
    asm volatile("mma.sync.aligned.m16n8k16.row.col.f32.bf16.bf16.f32 "      \
                 "{%0,%1,%2,%3}, {%4,%5,%6,%7}, {%8,%9}, {%0,%1,%2,%3};"     \
                 : "+f"((c)[0]), "+f"((c)[1]), "+f"((c)[2]), "+f"((c)[3])    \
                 : "r"((a)[0]), "r"((a)[1]), "r"((a)[2]), "r"((a)[3]),       \
                   "r"((b)[0]), "r"((b)[1]))

// C[M,TN] = A[M,128] @ B[128,TN]. 128 x TN block tile, 256 threads (8 warps),
// full K=128 staged once in SMEM as packed-bf16 hi/lo.
// FINAL=false: g_s[row] = C[row]      FINAL=true: OUT = C + bias
template<int TN, bool FINAL>
__global__ __launch_bounds__(256, 1) void mma_gemm(
    const float* __restrict__ A, const float* __restrict__ B,
    const float* __restrict__ bias, float* __restrict__ OUT, int M)
{
    constexpr int WM  = (TN == 128) ? 2 : 4;
    constexpr int WN  = 8 / WM;
    constexpr int MT  = 128 / WM / 16;
    constexpr int NT  = TN / WN / 8;
    constexpr int RPW = 128 / WM;
    constexpr int CPW = TN / WN;
    constexpr int SW  = 68;

    extern __shared__ uint32_t smw[];
    uint32_t* As_hi = smw;
    uint32_t* As_lo = As_hi + 128 * SW;
    uint32_t* Bs_hi = As_lo + 128 * SW;
    uint32_t* Bs_lo = Bs_hi + TN * SW;

    const int tid    = threadIdx.x;
    const int warpId = tid >> 5;
    const int lane   = tid & 31;
    const int g      = lane >> 2;
    const int tg     = lane & 3;
    const int wm     = warpId % WM;
    const int wn     = warpId / WM;
    const int blockRow = blockIdx.x * 128;

#pragma unroll
    for (int it = 0; it < 16; it++) {
        const int s   = tid + it * 256;
        const int row = s >> 5;
        const int c4  = (s & 31) << 2;
        float4 v = make_float4(0.f, 0.f, 0.f, 0.f);
        if (blockRow + row < M)
            v = *(const float4*)(A + (size_t)(blockRow + row) * 128 + c4);
        uint32_t h0, l0, h1, l1;
        pack2(v.x, v.y, h0, l0);
        pack2(v.z, v.w, h1, l1);
        const int w = row * SW + ((s & 31) << 1);
        *(uint2*)&As_hi[w] = make_uint2(h0, h1);
        *(uint2*)&As_lo[w] = make_uint2(l0, l1);
    }
#pragma unroll
    for (int it = 0; it < TN / 8; it++) {
        const int s   = tid + it * 256;
        const int col = s & (TN - 1);
        const int kb  = (s / TN) << 2;
        const float b0 = B[(size_t)(kb + 0) * TN + col];
        const float b1 = B[(size_t)(kb + 1) * TN + col];
        const float b2 = B[(size_t)(kb + 2) * TN + col];
        const float b3 = B[(size_t)(kb + 3) * TN + col];
        uint32_t h0, l0, h1, l1;
        pack2(b0, b1, h0, l0);
        pack2(b2, b3, h1, l1);
        const int w = col * SW + (kb >> 1);
        *(uint2*)&Bs_hi[w] = make_uint2(h0, h1);
        *(uint2*)&Bs_lo[w] = make_uint2(l0, l1);
    }
    __syncthreads();

    float acc[MT][NT][4];
#pragma unroll
    for (int mi = 0; mi < MT; mi++)
#pragma unroll
        for (int ni = 0; ni < NT; ni++)
#pragma unroll
            for (int q = 0; q < 4; q++) acc[mi][ni][q] = 0.0f;

#pragma unroll
    for (int kk = 0; kk < 8; kk++) {
        uint32_t ah[MT][4], al[MT][4];
#pragma unroll
        for (int mi = 0; mi < MT; mi++) {
            const int base = (wm * RPW + mi * 16 + g) * SW + kk * 8 + tg;
            ah[mi][0] = As_hi[base];
            ah[mi][1] = As_hi[base + 8 * SW];
            ah[mi][2] = As_hi[base + 4];
            ah[mi][3] = As_hi[base + 8 * SW + 4];
            al[mi][0] = As_lo[base];
            al[mi][1] = As_lo[base + 8 * SW];
            al[mi][2] = As_lo[base + 4];
            al[mi][3] = As_lo[base + 8 * SW + 4];
        }
        uint32_t bh[NT][2], bl[NT][2];
#pragma unroll
        for (int ni = 0; ni < NT; ni++) {
            const int base = (wn * CPW + ni * 8 + g) * SW + kk * 8 + tg;
            bh[ni][0] = Bs_hi[base];
            bh[ni][1] = Bs_hi[base + 4];
            bl[ni][0] = Bs_lo[base];
            bl[ni][1] = Bs_lo[base + 4];
        }
#pragma unroll
        for (int mi = 0; mi < MT; mi++)
#pragma unroll
            for (int ni = 0; ni < NT; ni++) {
                MMA_BF16(acc[mi][ni], ah[mi], bh[ni]);
                MMA_BF16(acc[mi][ni], al[mi], bh[ni]);
                MMA_BF16(acc[mi][ni], ah[mi], bl[ni]);
            }
    }

#pragma unroll
    for (int mi = 0; mi < MT; mi++) {
        const int rbase = blockRow + wm * RPW + mi * 16;
        const int r0 = rbase + g;
        const int r1 = rbase + g + 8;
#pragma unroll
        for (int ni = 0; ni < NT; ni++) {
            const int col = wn * CPW + ni * 8 + tg * 2;
            if (FINAL) {
                const float2 bb = __ldg((const float2*)(bias + col));
                if (r0 < M)
                    *(float2*)(OUT + (size_t)r0 * TN + col) =
                        make_float2(acc[mi][ni][0] + bb.x, acc[mi][ni][1] + bb.y);
                if (r1 < M)
                    *(float2*)(OUT + (size_t)r1 * TN + col) =
                        make_float2(acc[mi][ni][2] + bb.x, acc[mi][ni][3] + bb.y);
            } else {
                if (r0 < M)
                    *(float2*)(g_s + (size_t)r0 * TN + col) =
                        make_float2(acc[mi][ni][0], acc[mi][ni][1]);
                if (r1 < M)
                    *(float2*)(g_s + (size_t)r1 * TN + col) =
                        make_float2(acc[mi][ni][2], acc[mi][ni][3]);
            }
        }
    }
}

// --------------------------- neighbor aggregation ---------------------------
__global__ __launch_bounds__(256) void aggregate_kernel(
    const float* __restrict__ bias, int n)
{
    const int node = (blockIdx.x * 256 + threadIdx.x) >> 5;
    const int lane = threadIdx.x & 31;
    if (node >= n) return;

    const float dself = __ldg(&g_dinv[node]);
    const float4 sv = __ldg((const float4*)(g_s + (size_t)node * 128) + lane);
    float4 acc = make_float4(dself * sv.x, dself * sv.y,
                             dself * sv.z, dself * sv.w);
    int i = g_off[node];
    const int end = g_off[node + 1];

    for (; i + 4 <= end; i += 4) {
        const int r0 = __ldg(&g_csr[i]);
        const int r1 = __ldg(&g_csr[i + 1]);
        const int r2 = __ldg(&g_csr[i + 2]);
        const int r3 = __ldg(&g_csr[i + 3]);
        const float d0 = __ldg(&g_dinv[r0]);
        const float d1 = __ldg(&g_dinv[r1]);
        const float d2 = __ldg(&g_dinv[r2]);
        const float d3 = __ldg(&g_dinv[r3]);
        const float4 v0 = __ldg((const float4*)(g_s + (size_t)r0 * 128) + lane);
        const float4 v1 = __ldg((const float4*)(g_s + (size_t)r1 * 128) + lane);
        const float4 v2 = __ldg((const float4*)(g_s + (size_t)r2 * 128) + lane);
        const float4 v3 = __ldg((const float4*)(g_s + (size_t)r3 * 128) + lane);
        acc.x = fmaf(d0, v0.x, fmaf(d1, v1.x, fmaf(d2, v2.x, fmaf(d3, v3.x, acc.x))));
        acc.y = fmaf(d0, v0.y, fmaf(d1, v1.y, fmaf(d2, v2.y, fmaf(d3, v3.y, acc.y))));
        acc.z = fmaf(d0, v0.z, fmaf(d1, v1.z, fmaf(d2, v2.z, fmaf(d3, v3.z, acc.z))));
        acc.w = fmaf(d0, v0.w, fmaf(d1, v1.w, fmaf(d2, v2.w, fmaf(d3, v3.w, acc.w))));
    }
    for (; i < end; i++) {
        const int r = __ldg(&g_csr[i]);
        const float d = __ldg(&g_dinv[r]);
        const float4 v = __ldg((const float4*)(g_s + (size_t)r * 128) + lane);
        acc.x = fmaf(d, v.x, acc.x);
        acc.y = fmaf(d, v.y, acc.y);
        acc.z = fmaf(d, v.z, acc.z);
        acc.w = fmaf(d, v.w, acc.w);
    }

    const float4 b = __ldg((const float4*)bias + lane);
    float4 r;
    r.x = fmaxf(fmaf(dself, acc.x, b.x), 0.f);
    r.y = fmaxf(fmaf(dself, acc.y, b.y), 0.f);
    r.z = fmaxf(fmaf(dself, acc.z, b.z), 0.f);
    r.w = fmaxf(fmaf(dself, acc.w, b.w), 0.f);
    *((float4*)(g_h + (size_t)node * 128) + lane) = r;
}

// ------------------------------- launch -------------------------------------
extern "C" void kernel_launch(void* const* d_in, const int* in_sizes, int n_in,
                              void* d_out, int out_size) {
    const float* x  = (const float*)d_in[0];
    const void*  ei =               d_in[1];
    const float* W1 = (const float*)d_in[2];
    const float* b1 = (const float*)d_in[3];
    const float* W2 = (const float*)d_in[4];
    const float* b2 = (const float*)d_in[5];
    const float* Wl = (const float*)d_in[6];
    const float* bl = (const float*)d_in[7];
    float* out = (float*)d_out;

    const int n = in_sizes[0] / 128;   // 50000
    const int E = in_sizes[1] / 2;     // 640000

    float* h_dev = nullptr;  cudaGetSymbolAddress((void**)&h_dev, g_h);

    const int smem128 = (128 * 68 * 2 + 128 * 68 * 2) * 4;   // 139264 B
    const int smem64  = (128 * 68 * 2 +  64 * 68 * 2) * 4;   // 104448 B

    static cudaStream_t s1 = nullptr;
    static cudaEvent_t evFork = nullptr, evJoin = nullptr;
    if (s1 == nullptr) {
        cudaFuncSetAttribute(mma_gemm<128, false>,
                             cudaFuncAttributeMaxDynamicSharedMemorySize, smem128);
        cudaFuncSetAttribute(mma_gemm<64, true>,
                             cudaFuncAttributeMaxDynamicSharedMemorySize, smem64);
        cudaStreamCreateWithFlags(&s1, cudaStreamNonBlocking);
        cudaEventCreateWithFlags(&evFork, cudaEventDisableTiming);
        cudaEventCreateWithFlags(&evJoin, cudaEventDisableTiming);
    }

    const int eB = (E + 255) / 256;
    const int nB = (n + 255) / 256;
    const int sB = (n + SCAN_B - 1) / SCAN_B;    // scan blocks (196)
    const int gemmBlocks = (n + 127) / 128;
    const int aggBlocks  = (n * 32 + 255) / 256;

    // ---- fork: layer-1 GEMM (independent of graph prep) on side stream ----
    cudaEventRecord(evFork, 0);
    cudaStreamWaitEvent(s1, evFork, 0);
    mma_gemm<128, false><<<gemmBlocks, 256, smem128, s1>>>(x, W1, nullptr, nullptr, n);
    cudaEventRecord(evJoin, s1);

    // ---- CSR + normalization build on the main stream (overlapped) ----
    zero_detect_kernel<<<nB, 256>>>((const int*)ei, n);
    hist_kernel<<<eB, 256>>>(ei, E);
    scan_blocksum<<<sB, SCAN_B>>>(n);
    scan_tops<<<1, 256>>>(sB, n);
    scan_final<<<sB, SCAN_B>>>(n);
    fillcsr_kernel<<<eB, 256>>>(ei, E);

    // ---- join, then the serial tail ----
    cudaStreamWaitEvent(0, evJoin, 0);
    aggregate_kernel<<<aggBlocks, 256>>>(b1, n);

    mma_gemm<128, false><<<gemmBlocks, 256, smem128>>>(h_dev, W2, nullptr, nullptr, n);
    aggregate_kernel<<<aggBlocks, 256>>>(b2, n);

    mma_gemm<64, true><<<gemmBlocks, 256, smem64>>>(h_dev, Wl, bl, out, n);
}